// round 5
// baseline (speedup 1.0000x reference)
#include <cuda_runtime.h>
#include <cstdint>
#include <math.h>

// ---------------- problem constants ----------------
#define Bn  4
#define Sn  8192
#define Dn  1024
#define SDn 512
#define Mn  (Bn * Sn)          // 32768 rows
#define TS  128                // scan tile (rows) == BM
#define NT  (Sn / TS)          // 64 tiles per batch
#define RMS_EPS 1.1920929e-07f

// ---------------- GEMM tiling ----------------
#define BM 128
#define BN 128
#define BK 32
#define STAGES 3
#define SROW 36                              // padded floats per smem row (32+4)
#define STAGE_FLOATS ((BM + BN) * SROW)      // 9216 floats
#define STAGE_BYTES  (STAGE_FLOATS * 4)      // 36864 B
#define SMEM_BYTES   (STAGES * STAGE_BYTES)  // 110592 B

// ---------------- scratch ----------------
__device__ __align__(128) float g_xt[Mn * Dn];        // x, tf32-rna
__device__ __align__(128) float g_wb[2 * SDn * Dn];   // interleaved Wg/Wu rows, tf32-rna
__device__ __align__(128) float g_wo[Dn * SDn];       // W_out tf32-rna
__device__ __align__(128) float g_z[Mn * SDn];        // z then h
__device__ __align__(128) float g_tilesum[(Mn / TS) * SDn];
__device__ __align__(128) float g_rmsinv[Mn];

// ---------------- helpers ----------------
__device__ __forceinline__ uint32_t smem_u32(const void* p) {
    uint32_t a;
    asm("{ .reg .u64 t; cvta.to.shared.u64 t, %1; cvt.u32.u64 %0, t; }" : "=r"(a) : "l"(p));
    return a;
}
__device__ __forceinline__ void cp16(uint32_t d, const float* s) {
    asm volatile("cp.async.cg.shared.global [%0], [%1], 16;" :: "r"(d), "l"(s));
}
#define CP_COMMIT() asm volatile("cp.async.commit_group;" ::: "memory")
#define CP_WAIT(n)  asm volatile("cp.async.wait_group %0;" :: "n"(n) : "memory")

__device__ __forceinline__ void mma_tf32(float* c, const uint32_t* a, uint32_t b0, uint32_t b1) {
    asm volatile(
        "mma.sync.aligned.m16n8k8.row.col.f32.tf32.tf32.f32 "
        "{%0,%1,%2,%3}, {%4,%5,%6,%7}, {%8,%9}, {%0,%1,%2,%3};"
        : "+f"(c[0]), "+f"(c[1]), "+f"(c[2]), "+f"(c[3])
        : "r"(a[0]), "r"(a[1]), "r"(a[2]), "r"(a[3]), "r"(b0), "r"(b1));
}
__device__ __forceinline__ void ldsm4(uint32_t& r0, uint32_t& r1, uint32_t& r2, uint32_t& r3,
                                      uint32_t addr) {
    asm volatile("ldmatrix.sync.aligned.m8n8.x4.shared.b16 {%0,%1,%2,%3}, [%4];"
        : "=r"(r0), "=r"(r1), "=r"(r2), "=r"(r3) : "r"(addr));
}
__device__ __forceinline__ float tf32_rna(float v) {
    uint32_t u;
    asm("cvt.rna.tf32.f32 %0, %1;" : "=r"(u) : "f"(v));
    return __uint_as_float(u);
}
__device__ __forceinline__ float sigmoidf_fast(float g) {
    return 1.0f / (1.0f + __expf(-g));
}

// ===========================================================================
// conversion kernels: fp32 -> tf32(RNA) bits
// ===========================================================================
__global__ void k_cvt(const float4* __restrict__ src, float4* __restrict__ dst, int n4) {
    for (int i = blockIdx.x * blockDim.x + threadIdx.x; i < n4; i += gridDim.x * blockDim.x) {
        float4 v = src[i];
        v.x = tf32_rna(v.x); v.y = tf32_rna(v.y);
        v.z = tf32_rna(v.z); v.w = tf32_rna(v.w);
        dst[i] = v;
    }
}
__global__ void k_cvt_pair(const float4* __restrict__ wg, const float4* __restrict__ wu,
                           float4* __restrict__ dst) {
    const int RW = Dn / 4;
    const int total = SDn * RW;
    for (int i = blockIdx.x * blockDim.x + threadIdx.x; i < total; i += gridDim.x * blockDim.x) {
        int r = i / RW, c = i % RW;
        float4 vg = wg[i];
        vg.x = tf32_rna(vg.x); vg.y = tf32_rna(vg.y); vg.z = tf32_rna(vg.z); vg.w = tf32_rna(vg.w);
        dst[(size_t)(2 * r) * RW + c] = vg;
        float4 vu = wu[i];
        vu.x = tf32_rna(vu.x); vu.y = tf32_rna(vu.y); vu.z = tf32_rna(vu.z); vu.w = tf32_rna(vu.w);
        dst[(size_t)(2 * r + 1) * RW + c] = vu;
    }
}

// ===========================================================================
// shared GEMM mainloop. A: [M x K] rm, B: [N x K] rm (C = A @ B^T), tile 128x128
// 256 threads, warp grid 4(M) x 2(N), warp tile 32(M) x 64(N)
// BK=32, 3 stages, fragment double-buffering across k8 steps
// ===========================================================================
struct Frag { float acc[2][8][4]; };

template<int KTOT>
__device__ __forceinline__ void gemm_mainloop(const float* __restrict__ A,
                                              const float* __restrict__ B,
                                              int m0, int n0, char* smem, Frag& f) {
    const int t = threadIdx.x;
    const int lr = t >> 1;            // row 0..127
    const int ls = t & 1;             // half-row: floats [ls*16, ls*16+16)
    const uint32_t sb0 = smem_u32(smem);

    const float* Ag = A + (size_t)(m0 + lr) * KTOT + ls * 16;
    const float* Bg = B + (size_t)(n0 + lr) * KTOT + ls * 16;
    const uint32_t sA = sb0 + lr * (SROW * 4) + ls * 64;
    const uint32_t sB = sA + BM * (SROW * 4);

    const int iters = KTOT / BK;

    #pragma unroll
    for (int i = 0; i < 2; i++)
        #pragma unroll
        for (int j = 0; j < 8; j++)
            #pragma unroll
            for (int q = 0; q < 4; q++) f.acc[i][j][q] = 0.f;

    #pragma unroll
    for (int p = 0; p < STAGES - 1; p++) {
        const float* ag = Ag + p * BK;
        const float* bg = Bg + p * BK;
        uint32_t da = sA + p * STAGE_BYTES, db = sB + p * STAGE_BYTES;
        #pragma unroll
        for (int sgm = 0; sgm < 4; sgm++) {
            cp16(da + sgm * 16, ag + sgm * 4);
            cp16(db + sgm * 16, bg + sgm * 4);
        }
        CP_COMMIT();
    }

    const int wid = t >> 5, lane = t & 31;
    const int wm = wid & 3, wn = wid >> 2;
    const int mrow = wm * 32, nb = wn * 64;

    // ldmatrix per-lane byte offsets (within a stage)
    const uint32_t arow = ((lane >> 3) & 1) * 8 + (lane & 7);
    const uint32_t acol = ((lane >> 4) & 1) * 4;
    const uint32_t a_off = ((mrow + arow) * SROW + acol) * 4;
    const uint32_t brow = ((lane >> 4) & 1) * 8 + (lane & 7);
    const uint32_t bcol = ((lane >> 3) & 1) * 4;
    const uint32_t b_off = (BM * SROW + (nb + brow) * SROW + bcol) * 4;

    uint32_t a[2][2][4];       // [buf][mt][4]
    uint32_t b[2][8][2];       // [buf][nt][2]

    int rs = 0;
    for (int it = 0; it < iters; it++) {
        CP_WAIT(STAGES - 2);
        __syncthreads();

        if (it + STAGES - 1 < iters) {
            int ws = rs + STAGES - 1; if (ws >= STAGES) ws -= STAGES;
            const float* ag = Ag + (it + STAGES - 1) * BK;
            const float* bg = Bg + (it + STAGES - 1) * BK;
            uint32_t da = sA + ws * STAGE_BYTES, db = sB + ws * STAGE_BYTES;
            #pragma unroll
            for (int sgm = 0; sgm < 4; sgm++) {
                cp16(da + sgm * 16, ag + sgm * 4);
                cp16(db + sgm * 16, bg + sgm * 4);
            }
        }
        CP_COMMIT();

        const uint32_t sbase = sb0 + rs * STAGE_BYTES;

        // prefetch fragments for k8-step 0
        ldsm4(a[0][0][0], a[0][0][1], a[0][0][2], a[0][0][3], sbase + a_off);
        ldsm4(a[0][1][0], a[0][1][1], a[0][1][2], a[0][1][3], sbase + a_off + 16 * SROW * 4);
        #pragma unroll
        for (int p = 0; p < 4; p++)
            ldsm4(b[0][2*p][0], b[0][2*p][1], b[0][2*p+1][0], b[0][2*p+1][1],
                  sbase + b_off + p * 16 * SROW * 4);

        #pragma unroll
        for (int s = 0; s < BK / 8; s++) {
            const int cur = s & 1, nxt = cur ^ 1;
            if (s < BK / 8 - 1) {     // prefetch next step's fragments
                const uint32_t ko = (s + 1) * 8 * 4;
                ldsm4(a[nxt][0][0], a[nxt][0][1], a[nxt][0][2], a[nxt][0][3],
                      sbase + a_off + ko);
                ldsm4(a[nxt][1][0], a[nxt][1][1], a[nxt][1][2], a[nxt][1][3],
                      sbase + a_off + 16 * SROW * 4 + ko);
                #pragma unroll
                for (int p = 0; p < 4; p++)
                    ldsm4(b[nxt][2*p][0], b[nxt][2*p][1], b[nxt][2*p+1][0], b[nxt][2*p+1][1],
                          sbase + b_off + p * 16 * SROW * 4 + ko);
            }
            #pragma unroll
            for (int nt = 0; nt < 8; nt++) {
                mma_tf32(f.acc[0][nt], a[cur][0], b[cur][nt][0], b[cur][nt][1]);
                mma_tf32(f.acc[1][nt], a[cur][1], b[cur][nt][0], b[cur][nt][1]);
            }
        }
        rs++; if (rs == STAGES) rs = 0;
    }
    CP_WAIT(0);
    __syncthreads();
}

// ===========================================================================
// k1: C = x @ Wb^T (interleaved weights, N=1024). Epilogue: z = sigmoid(g)*u,
// write g_z, per-CTA 128-row tile column sums (shuffle-reduced).
// ===========================================================================
__global__ void __launch_bounds__(256, 2) k1_gemm() {
    extern __shared__ char smem[];
    const int n0 = blockIdx.x * BN;
    const int m0 = blockIdx.y * BM;
    Frag f;
    gemm_mainloop<Dn>(g_xt, g_wb, m0, n0, smem, f);

    const int t = threadIdx.x;
    const int wid = t >> 5, lane = t & 31;
    const int wm = wid & 3, wn = wid >> 2;
    const int gr = lane >> 2, gc = lane & 3;
    const int zbase = n0 >> 1;

    float* csum = (float*)smem;
    if (t < 64) csum[t] = 0.f;
    __syncthreads();

    #pragma unroll
    for (int nt = 0; nt < 8; nt++) {
        float cs = 0.f;
        #pragma unroll
        for (int mt = 0; mt < 2; mt++) {
            const int r0 = m0 + wm * 32 + mt * 16 + gr;
            const int zc = zbase + wn * 32 + nt * 4 + gc;
            float z0 = f.acc[mt][nt][1] * sigmoidf_fast(f.acc[mt][nt][0]);
            float z1 = f.acc[mt][nt][3] * sigmoidf_fast(f.acc[mt][nt][2]);
            g_z[(size_t)r0 * SDn + zc] = z0;
            g_z[(size_t)(r0 + 8) * SDn + zc] = z1;
            cs += z0 + z1;
        }
        // reduce over gr lanes (same gc): offsets 4, 8, 16
        cs += __shfl_xor_sync(0xffffffffu, cs, 4);
        cs += __shfl_xor_sync(0xffffffffu, cs, 8);
        cs += __shfl_xor_sync(0xffffffffu, cs, 16);
        if (gr == 0)
            atomicAdd(&csum[wn * 32 + nt * 4 + gc], cs);
    }
    __syncthreads();
    if (t < 64)
        g_tilesum[(size_t)blockIdx.y * SDn + zbase + t] = csum[t];
}

// ===========================================================================
// k2: exclusive prefix over tiles per (b,k) channel
// ===========================================================================
__global__ void k2_tileprefix() {
    int idx = blockIdx.x * blockDim.x + threadIdx.x;
    int b = idx / SDn, k = idx % SDn;
    float run = 0.f;
    for (int t = 0; t < NT; t++) {
        size_t off = (size_t)(b * NT + t) * SDn + k;
        float v = g_tilesum[off];
        g_tilesum[off] = run;
        run += v;
    }
}

// ===========================================================================
// k3a: in-tile scan + /denom, rewrite g_z with tf32-rna(h), per-row rms_inv
// ===========================================================================
__global__ void __launch_bounds__(512) k3a_scan() {
    const int mt = blockIdx.x;
    const int t = mt & (NT - 1);
    const int k = threadIdx.x;
    const int warp = k >> 5, lane = k & 31;
    const int base = mt * TS;

    __shared__ float ssp[TS][16];

    float carry = g_tilesum[(size_t)mt * SDn + k];

    #pragma unroll 4
    for (int r = 0; r < TS; r++) {
        const size_t off = (size_t)(base + r) * SDn + k;
        carry += g_z[off];
        float h = __fdividef(carry, (float)(t * TS + r + 1));
        h = tf32_rna(h);
        g_z[off] = h;
        float sq = h * h;
        #pragma unroll
        for (int o = 16; o > 0; o >>= 1) sq += __shfl_xor_sync(0xffffffffu, sq, o);
        if (lane == 0) ssp[r][warp] = sq;
    }
    __syncthreads();
    if (k < TS) {
        float s = 0.f;
        #pragma unroll
        for (int w = 0; w < 16; w++) s += ssp[k][w];
        g_rmsinv[base + k] = rsqrtf(s * (1.0f / SDn) + RMS_EPS);
    }
}

// ===========================================================================
// k3b: out = rms_inv[m] * (h @ Wo^T), M=32768, N=1024, K=512
// ===========================================================================
__global__ void __launch_bounds__(256, 2) k3b_gemm(float* __restrict__ out) {
    extern __shared__ char smem[];
    const int n0 = blockIdx.x * BN;
    const int m0 = blockIdx.y * BM;
    Frag f;
    gemm_mainloop<SDn>(g_z, g_wo, m0, n0, smem, f);

    const int t = threadIdx.x;
    const int wid = t >> 5, lane = t & 31;
    const int wm = wid & 3, wn = wid >> 2;
    const int gr = lane >> 2, gc = lane & 3;

    #pragma unroll
    for (int mt = 0; mt < 2; mt++) {
        const int r0 = m0 + wm * 32 + mt * 16 + gr;
        const float ri0 = g_rmsinv[r0];
        const float ri1 = g_rmsinv[r0 + 8];
        #pragma unroll
        for (int nt = 0; nt < 8; nt++) {
            const int col = n0 + wn * 64 + nt * 8 + gc * 2;
            float2 v0 = { f.acc[mt][nt][0] * ri0, f.acc[mt][nt][1] * ri0 };
            float2 v1 = { f.acc[mt][nt][2] * ri1, f.acc[mt][nt][3] * ri1 };
            *(float2*)&out[(size_t)r0 * Dn + col] = v0;
            *(float2*)&out[(size_t)(r0 + 8) * Dn + col] = v1;
        }
    }
}

// ===========================================================================
// host side
// ===========================================================================
extern "C" void kernel_launch(void* const* d_in, const int* in_sizes, int n_in,
                              void* d_out, int out_size) {
    const float* x  = (const float*)d_in[0];
    const float* Wu = (const float*)d_in[1];
    const float* Wg = (const float*)d_in[2];
    const float* Wo = (const float*)d_in[3];
    float* out = (float*)d_out;

    void *pxt, *pwb, *pwo;
    cudaGetSymbolAddress(&pxt, g_xt);
    cudaGetSymbolAddress(&pwb, g_wb);
    cudaGetSymbolAddress(&pwo, g_wo);

    cudaFuncSetAttribute(k1_gemm,  cudaFuncAttributeMaxDynamicSharedMemorySize, SMEM_BYTES);
    cudaFuncSetAttribute(k3b_gemm, cudaFuncAttributeMaxDynamicSharedMemorySize, SMEM_BYTES);

    k_cvt<<<4096, 256>>>((const float4*)x, (float4*)pxt, Mn * Dn / 4);
    k_cvt_pair<<<512, 256>>>((const float4*)Wg, (const float4*)Wu, (float4*)pwb);
    k_cvt<<<512, 256>>>((const float4*)Wo, (float4*)pwo, Dn * SDn / 4);

    k1_gemm<<<dim3(2 * SDn / BN, Mn / BM), 256, SMEM_BYTES>>>();
    k2_tileprefix<<<(Bn * SDn) / 256, 256>>>();
    k3a_scan<<<Mn / TS, 512>>>();
    k3b_gemm<<<dim3(Dn / BN, Mn / BM), 256, SMEM_BYTES>>>(out);
}

// round 6
// speedup vs baseline: 1.2199x; 1.2199x over previous
#include <cuda_runtime.h>
#include <cstdint>
#include <math.h>

// ---------------- problem constants ----------------
#define Bn  4
#define Sn  8192
#define Dn  1024
#define SDn 512
#define Mn  (Bn * Sn)          // 32768 rows
#define TS  128                // scan tile (rows) == BM
#define NT  (Sn / TS)          // 64 tiles per batch
#define RMS_EPS 1.1920929e-07f

// ---------------- GEMM tiling ----------------
#define BM 128
#define BN 256
#define BK 32
#define STAGES 3
#define SROW 36                              // padded floats per smem row (32+4)
#define STAGE_FLOATS ((BM + BN) * SROW)      // 13824 floats
#define STAGE_BYTES  (STAGE_FLOATS * 4)      // 55296 B
#define SMEM_BYTES   (STAGES * STAGE_BYTES)  // 165888 B

// ---------------- scratch ----------------
__device__ __align__(128) float g_xt[Mn * Dn];        // x, tf32-rna
__device__ __align__(128) float g_wb[2 * SDn * Dn];   // interleaved Wg/Wu rows, tf32-rna
__device__ __align__(128) float g_wo[Dn * SDn];       // W_out tf32-rna
__device__ __align__(128) float g_z[Mn * SDn];        // z then h
__device__ __align__(128) float g_tilesum[(Mn / TS) * SDn];
__device__ __align__(128) float g_rmsinv[Mn];

// ---------------- helpers ----------------
__device__ __forceinline__ uint32_t smem_u32(const void* p) {
    uint32_t a;
    asm("{ .reg .u64 t; cvta.to.shared.u64 t, %1; cvt.u32.u64 %0, t; }" : "=r"(a) : "l"(p));
    return a;
}
__device__ __forceinline__ void cp16(uint32_t d, const float* s) {
    asm volatile("cp.async.cg.shared.global [%0], [%1], 16;" :: "r"(d), "l"(s));
}
#define CP_COMMIT() asm volatile("cp.async.commit_group;" ::: "memory")
#define CP_WAIT(n)  asm volatile("cp.async.wait_group %0;" :: "n"(n) : "memory")

__device__ __forceinline__ void mma_tf32(float* c, const uint32_t* a, uint32_t b0, uint32_t b1) {
    asm volatile(
        "mma.sync.aligned.m16n8k8.row.col.f32.tf32.tf32.f32 "
        "{%0,%1,%2,%3}, {%4,%5,%6,%7}, {%8,%9}, {%0,%1,%2,%3};"
        : "+f"(c[0]), "+f"(c[1]), "+f"(c[2]), "+f"(c[3])
        : "r"(a[0]), "r"(a[1]), "r"(a[2]), "r"(a[3]), "r"(b0), "r"(b1));
}
__device__ __forceinline__ void ldsm4(uint32_t& r0, uint32_t& r1, uint32_t& r2, uint32_t& r3,
                                      uint32_t addr) {
    asm volatile("ldmatrix.sync.aligned.m8n8.x4.shared.b16 {%0,%1,%2,%3}, [%4];"
        : "=r"(r0), "=r"(r1), "=r"(r2), "=r"(r3) : "r"(addr));
}
__device__ __forceinline__ float tf32_rna(float v) {
    uint32_t u;
    asm("cvt.rna.tf32.f32 %0, %1;" : "=r"(u) : "f"(v));
    return __uint_as_float(u);
}
__device__ __forceinline__ float sigmoidf_fast(float g) {
    return 1.0f / (1.0f + __expf(-g));
}

// ===========================================================================
// conversion kernels: fp32 -> tf32(RNA) bits
// ===========================================================================
__global__ void k_cvt(const float4* __restrict__ src, float4* __restrict__ dst, int n4) {
    for (int i = blockIdx.x * blockDim.x + threadIdx.x; i < n4; i += gridDim.x * blockDim.x) {
        float4 v = src[i];
        v.x = tf32_rna(v.x); v.y = tf32_rna(v.y);
        v.z = tf32_rna(v.z); v.w = tf32_rna(v.w);
        dst[i] = v;
    }
}
__global__ void k_cvt_pair(const float4* __restrict__ wg, const float4* __restrict__ wu,
                           float4* __restrict__ dst) {
    const int RW = Dn / 4;
    const int total = SDn * RW;
    for (int i = blockIdx.x * blockDim.x + threadIdx.x; i < total; i += gridDim.x * blockDim.x) {
        int r = i / RW, c = i % RW;
        float4 vg = wg[i];
        vg.x = tf32_rna(vg.x); vg.y = tf32_rna(vg.y); vg.z = tf32_rna(vg.z); vg.w = tf32_rna(vg.w);
        dst[(size_t)(2 * r) * RW + c] = vg;
        float4 vu = wu[i];
        vu.x = tf32_rna(vu.x); vu.y = tf32_rna(vu.y); vu.z = tf32_rna(vu.z); vu.w = tf32_rna(vu.w);
        dst[(size_t)(2 * r + 1) * RW + c] = vu;
    }
}

// ===========================================================================
// GEMM mainloop. A: [M x K] rm, B: [N x K] rm (C = A @ B^T), CTA tile 128x256
// 256 threads, warp grid 2(M) x 4(N), warp tile 64(M) x 64(N)
// Per k8-step/warp: 8 ldmatrix.x4 feed 32 MMAs (4:1) — crossbar relief.
// ===========================================================================
struct Frag { float acc[4][8][4]; };

template<int KTOT>
__device__ __forceinline__ void gemm_mainloop(const float* __restrict__ A,
                                              const float* __restrict__ B,
                                              int m0, int n0, char* smem, Frag& f) {
    const int t = threadIdx.x;
    const uint32_t sb0 = smem_u32(smem);
    const int lrow = t >> 3;          // 0..31
    const int lseg = t & 7;           // 16B chunk within 128B row

    const int iters = KTOT / BK;

    #pragma unroll
    for (int i = 0; i < 4; i++)
        #pragma unroll
        for (int j = 0; j < 8; j++)
            #pragma unroll
            for (int q = 0; q < 4; q++) f.acc[i][j][q] = 0.f;

    // stage loader: 12 chunks/thread (i<4 -> A rows 0..127, i>=4 -> B rows 0..255)
    #pragma unroll
    for (int p = 0; p < STAGES - 1; p++) {
        const int k0 = p * BK;
        #pragma unroll
        for (int i = 0; i < 12; i++) {
            if (i < 4) {
                const int row = 32 * i + lrow;
                cp16(sb0 + p * STAGE_BYTES + (row * SROW + lseg * 4) * 4,
                     A + (size_t)(m0 + row) * KTOT + k0 + lseg * 4);
            } else {
                const int row = 32 * (i - 4) + lrow;
                cp16(sb0 + p * STAGE_BYTES + ((BM + row) * SROW + lseg * 4) * 4,
                     B + (size_t)(n0 + row) * KTOT + k0 + lseg * 4);
            }
        }
        CP_COMMIT();
    }

    const int wid = t >> 5, lane = t & 31;
    const int wm = wid & 1, wn = wid >> 1;
    const int mrow = wm * 64, nb = wn * 64;

    // ldmatrix per-lane byte offsets (within a stage)
    const uint32_t arow = ((lane >> 3) & 1) * 8 + (lane & 7);
    const uint32_t acol = ((lane >> 4) & 1) * 4;
    const uint32_t a_off = ((mrow + arow) * SROW + acol) * 4;
    const uint32_t brow = ((lane >> 4) & 1) * 8 + (lane & 7);
    const uint32_t bcol = ((lane >> 3) & 1) * 4;
    const uint32_t b_off = ((BM + nb + brow) * SROW + bcol) * 4;

    int rs = 0;
    for (int it = 0; it < iters; it++) {
        CP_WAIT(STAGES - 2);
        __syncthreads();

        if (it + STAGES - 1 < iters) {
            int ws = rs + STAGES - 1; if (ws >= STAGES) ws -= STAGES;
            const int k0 = (it + STAGES - 1) * BK;
            #pragma unroll
            for (int i = 0; i < 12; i++) {
                if (i < 4) {
                    const int row = 32 * i + lrow;
                    cp16(sb0 + ws * STAGE_BYTES + (row * SROW + lseg * 4) * 4,
                         A + (size_t)(m0 + row) * KTOT + k0 + lseg * 4);
                } else {
                    const int row = 32 * (i - 4) + lrow;
                    cp16(sb0 + ws * STAGE_BYTES + ((BM + row) * SROW + lseg * 4) * 4,
                         B + (size_t)(n0 + row) * KTOT + k0 + lseg * 4);
                }
            }
        }
        CP_COMMIT();

        const uint32_t sbase = sb0 + rs * STAGE_BYTES;

        #pragma unroll
        for (int s = 0; s < BK / 8; s++) {
            const uint32_t ko = s * 8 * 4;
            uint32_t a[4][4];
            #pragma unroll
            for (int mt = 0; mt < 4; mt++)
                ldsm4(a[mt][0], a[mt][1], a[mt][2], a[mt][3],
                      sbase + a_off + mt * 16 * SROW * 4 + ko);
            uint32_t b[8][2];
            #pragma unroll
            for (int p = 0; p < 4; p++)
                ldsm4(b[2*p][0], b[2*p][1], b[2*p+1][0], b[2*p+1][1],
                      sbase + b_off + p * 16 * SROW * 4 + ko);
            #pragma unroll
            for (int nt = 0; nt < 8; nt++)
                #pragma unroll
                for (int mt = 0; mt < 4; mt++)
                    mma_tf32(f.acc[mt][nt], a[mt], b[nt][0], b[nt][1]);
        }
        rs++; if (rs == STAGES) rs = 0;
    }
    CP_WAIT(0);
    __syncthreads();
}

// ===========================================================================
// k1: C = x @ Wb^T (interleaved weights, N=1024 stacked). Epilogue:
// z = sigmoid(g)*u, write g_z, per-CTA 128-row tile column sums (128 z-cols).
// ===========================================================================
__global__ void __launch_bounds__(256, 1) k1_gemm() {
    extern __shared__ char smem[];
    const int n0 = blockIdx.x * BN;
    const int m0 = blockIdx.y * BM;
    Frag f;
    gemm_mainloop<Dn>(g_xt, g_wb, m0, n0, smem, f);

    const int t = threadIdx.x;
    const int wid = t >> 5, lane = t & 31;
    const int wm = wid & 1, wn = wid >> 1;
    const int gr = lane >> 2, gc = lane & 3;
    const int zbase = n0 >> 1;             // 128 z-cols per CTA

    float* csum = (float*)smem;
    if (t < 128) csum[t] = 0.f;
    __syncthreads();

    #pragma unroll
    for (int nt = 0; nt < 8; nt++) {
        float cs = 0.f;
        #pragma unroll
        for (int mt = 0; mt < 4; mt++) {
            const int r0 = m0 + wm * 64 + mt * 16 + gr;
            const int zc = zbase + wn * 32 + nt * 4 + gc;
            float z0 = f.acc[mt][nt][1] * sigmoidf_fast(f.acc[mt][nt][0]);
            float z1 = f.acc[mt][nt][3] * sigmoidf_fast(f.acc[mt][nt][2]);
            g_z[(size_t)r0 * SDn + zc] = z0;
            g_z[(size_t)(r0 + 8) * SDn + zc] = z1;
            cs += z0 + z1;
        }
        cs += __shfl_xor_sync(0xffffffffu, cs, 4);
        cs += __shfl_xor_sync(0xffffffffu, cs, 8);
        cs += __shfl_xor_sync(0xffffffffu, cs, 16);
        if (gr == 0)
            atomicAdd(&csum[wn * 32 + nt * 4 + gc], cs);
    }
    __syncthreads();
    if (t < 128)
        g_tilesum[(size_t)blockIdx.y * SDn + zbase + t] = csum[t];
}

// ===========================================================================
// k2: exclusive prefix over tiles per (b,k) channel
// ===========================================================================
__global__ void k2_tileprefix() {
    int idx = blockIdx.x * blockDim.x + threadIdx.x;
    int b = idx / SDn, k = idx % SDn;
    float run = 0.f;
    for (int t = 0; t < NT; t++) {
        size_t off = (size_t)(b * NT + t) * SDn + k;
        float v = g_tilesum[off];
        g_tilesum[off] = run;
        run += v;
    }
}

// ===========================================================================
// k3a: in-tile scan + /denom, rewrite g_z with tf32-rna(h), per-row rms_inv
// ===========================================================================
__global__ void __launch_bounds__(512) k3a_scan() {
    const int mt = blockIdx.x;
    const int t = mt & (NT - 1);
    const int k = threadIdx.x;
    const int warp = k >> 5, lane = k & 31;
    const int base = mt * TS;

    __shared__ float ssp[TS][16];

    float carry = g_tilesum[(size_t)mt * SDn + k];

    #pragma unroll 4
    for (int r = 0; r < TS; r++) {
        const size_t off = (size_t)(base + r) * SDn + k;
        carry += g_z[off];
        float h = __fdividef(carry, (float)(t * TS + r + 1));
        h = tf32_rna(h);
        g_z[off] = h;
        float sq = h * h;
        #pragma unroll
        for (int o = 16; o > 0; o >>= 1) sq += __shfl_xor_sync(0xffffffffu, sq, o);
        if (lane == 0) ssp[r][warp] = sq;
    }
    __syncthreads();
    if (k < TS) {
        float s = 0.f;
        #pragma unroll
        for (int w = 0; w < 16; w++) s += ssp[k][w];
        g_rmsinv[base + k] = rsqrtf(s * (1.0f / SDn) + RMS_EPS);
    }
}

// ===========================================================================
// k3b: out = rms_inv[m] * (h @ Wo^T), M=32768, N=1024, K=512
// ===========================================================================
__global__ void __launch_bounds__(256, 1) k3b_gemm(float* __restrict__ out) {
    extern __shared__ char smem[];
    const int n0 = blockIdx.x * BN;
    const int m0 = blockIdx.y * BM;
    Frag f;
    gemm_mainloop<SDn>(g_z, g_wo, m0, n0, smem, f);

    const int t = threadIdx.x;
    const int wid = t >> 5, lane = t & 31;
    const int wm = wid & 1, wn = wid >> 1;
    const int gr = lane >> 2, gc = lane & 3;

    #pragma unroll
    for (int mt = 0; mt < 4; mt++) {
        const int r0 = m0 + wm * 64 + mt * 16 + gr;
        const float ri0 = g_rmsinv[r0];
        const float ri1 = g_rmsinv[r0 + 8];
        #pragma unroll
        for (int nt = 0; nt < 8; nt++) {
            const int col = n0 + wn * 64 + nt * 8 + gc * 2;
            float2 v0 = { f.acc[mt][nt][0] * ri0, f.acc[mt][nt][1] * ri0 };
            float2 v1 = { f.acc[mt][nt][2] * ri1, f.acc[mt][nt][3] * ri1 };
            *(float2*)&out[(size_t)r0 * Dn + col] = v0;
            *(float2*)&out[(size_t)(r0 + 8) * Dn + col] = v1;
        }
    }
}

// ===========================================================================
// host side
// ===========================================================================
extern "C" void kernel_launch(void* const* d_in, const int* in_sizes, int n_in,
                              void* d_out, int out_size) {
    const float* x  = (const float*)d_in[0];
    const float* Wu = (const float*)d_in[1];
    const float* Wg = (const float*)d_in[2];
    const float* Wo = (const float*)d_in[3];
    float* out = (float*)d_out;

    void *pxt, *pwb, *pwo;
    cudaGetSymbolAddress(&pxt, g_xt);
    cudaGetSymbolAddress(&pwb, g_wb);
    cudaGetSymbolAddress(&pwo, g_wo);

    cudaFuncSetAttribute(k1_gemm,  cudaFuncAttributeMaxDynamicSharedMemorySize, SMEM_BYTES);
    cudaFuncSetAttribute(k3b_gemm, cudaFuncAttributeMaxDynamicSharedMemorySize, SMEM_BYTES);

    k_cvt<<<4096, 256>>>((const float4*)x, (float4*)pxt, Mn * Dn / 4);
    k_cvt_pair<<<512, 256>>>((const float4*)Wg, (const float4*)Wu, (float4*)pwb);
    k_cvt<<<512, 256>>>((const float4*)Wo, (float4*)pwo, Dn * SDn / 4);

    k1_gemm<<<dim3(2 * SDn / BN, Mn / BM), 256, SMEM_BYTES>>>();
    k2_tileprefix<<<(Bn * SDn) / 256, 256>>>();
    k3a_scan<<<Mn / TS, 512>>>();
    k3b_gemm<<<dim3(Dn / BN, Mn / BM), 256, SMEM_BYTES>>>(out);
}

// round 7
// speedup vs baseline: 1.2974x; 1.0635x over previous
#include <cuda_runtime.h>
#include <cstdint>
#include <math.h>

// ---------------- problem constants ----------------
#define Bn  4
#define Sn  8192
#define Dn  1024
#define SDn 512
#define Mn  (Bn * Sn)          // 32768 rows
#define TS  128                // scan tile (rows) == BM
#define NT  (Sn / TS)          // 64 tiles per batch
#define RMS_EPS 1.1920929e-07f

// ---------------- GEMM tiling ----------------
#define BM 128
#define BN 256
#define BK 64
#define STAGES 2
#define SROW 68                              // padded floats per smem row (64+4)
#define STAGE_FLOATS ((BM + BN) * SROW)      // 26112 floats
#define STAGE_BYTES  (STAGE_FLOATS * 4)      // 104448 B
#define SMEM_BYTES   (STAGES * STAGE_BYTES)  // 208896 B

// ---------------- scratch ----------------
__device__ __align__(128) float g_wb[2 * SDn * Dn];   // interleaved Wg/Wu rows, tf32-rna
__device__ __align__(128) float g_wo[Dn * SDn];       // W_out tf32-rna
__device__ __align__(128) float g_z[Mn * SDn];        // z then h
__device__ __align__(128) float g_tilesum[(Mn / TS) * SDn];
__device__ __align__(128) float g_rmsinv[Mn];

// ---------------- helpers ----------------
__device__ __forceinline__ uint32_t smem_u32(const void* p) {
    uint32_t a;
    asm("{ .reg .u64 t; cvta.to.shared.u64 t, %1; cvt.u32.u64 %0, t; }" : "=r"(a) : "l"(p));
    return a;
}
__device__ __forceinline__ void cp16(uint32_t d, const float* s) {
    asm volatile("cp.async.cg.shared.global [%0], [%1], 16;" :: "r"(d), "l"(s));
}
#define CP_COMMIT() asm volatile("cp.async.commit_group;" ::: "memory")
#define CP_WAIT(n)  asm volatile("cp.async.wait_group %0;" :: "n"(n) : "memory")

__device__ __forceinline__ void mma_tf32(float* c, const uint32_t* a, uint32_t b0, uint32_t b1) {
    asm volatile(
        "mma.sync.aligned.m16n8k8.row.col.f32.tf32.tf32.f32 "
        "{%0,%1,%2,%3}, {%4,%5,%6,%7}, {%8,%9}, {%0,%1,%2,%3};"
        : "+f"(c[0]), "+f"(c[1]), "+f"(c[2]), "+f"(c[3])
        : "r"(a[0]), "r"(a[1]), "r"(a[2]), "r"(a[3]), "r"(b0), "r"(b1));
}
__device__ __forceinline__ void ldsm4(uint32_t& r0, uint32_t& r1, uint32_t& r2, uint32_t& r3,
                                      uint32_t addr) {
    asm volatile("ldmatrix.sync.aligned.m8n8.x4.shared.b16 {%0,%1,%2,%3}, [%4];"
        : "=r"(r0), "=r"(r1), "=r"(r2), "=r"(r3) : "r"(addr));
}
__device__ __forceinline__ uint32_t tf32_rna_bits(uint32_t v) {
    uint32_t u;
    asm("cvt.rna.tf32.f32 %0, %1;" : "=r"(u) : "f"(__uint_as_float(v)));
    return u;
}
__device__ __forceinline__ float tf32_rna(float v) {
    uint32_t u;
    asm("cvt.rna.tf32.f32 %0, %1;" : "=r"(u) : "f"(v));
    return __uint_as_float(u);
}
__device__ __forceinline__ float sigmoidf_fast(float g) {
    return 1.0f / (1.0f + __expf(-g));
}

// ===========================================================================
// weight conversion kernels: fp32 -> tf32(RNA) bits
// ===========================================================================
__global__ void k_cvt(const float4* __restrict__ src, float4* __restrict__ dst, int n4) {
    for (int i = blockIdx.x * blockDim.x + threadIdx.x; i < n4; i += gridDim.x * blockDim.x) {
        float4 v = src[i];
        v.x = tf32_rna(v.x); v.y = tf32_rna(v.y);
        v.z = tf32_rna(v.z); v.w = tf32_rna(v.w);
        dst[i] = v;
    }
}
__global__ void k_cvt_pair(const float4* __restrict__ wg, const float4* __restrict__ wu,
                           float4* __restrict__ dst) {
    const int RW = Dn / 4;
    const int total = SDn * RW;
    for (int i = blockIdx.x * blockDim.x + threadIdx.x; i < total; i += gridDim.x * blockDim.x) {
        int r = i / RW, c = i % RW;
        float4 vg = wg[i];
        vg.x = tf32_rna(vg.x); vg.y = tf32_rna(vg.y); vg.z = tf32_rna(vg.z); vg.w = tf32_rna(vg.w);
        dst[(size_t)(2 * r) * RW + c] = vg;
        float4 vu = wu[i];
        vu.x = tf32_rna(vu.x); vu.y = tf32_rna(vu.y); vu.z = tf32_rna(vu.z); vu.w = tf32_rna(vu.w);
        dst[(size_t)(2 * r + 1) * RW + c] = vu;
    }
}

// ===========================================================================
// GEMM mainloop. A: [M x K] rm, B: [N x K] rm (C = A @ B^T), CTA tile 128x256
// 256 threads, warp grid 2(M) x 4(N), warp tile 64(M) x 64(N)
// BK=64, 2 stages (16 barriers for K=1024). CVTA: round A frags to tf32-RNA
// in-register after ldmatrix (lets k1 read raw fp32 x, no pre-pass).
// ===========================================================================
struct Frag { float acc[4][8][4]; };

template<int KTOT, bool CVTA>
__device__ __forceinline__ void gemm_mainloop(const float* __restrict__ A,
                                              const float* __restrict__ B,
                                              int m0, int n0, char* smem, Frag& f) {
    const int t = threadIdx.x;
    const uint32_t sb0 = smem_u32(smem);
    const int lrow = t >> 4;          // 0..15
    const int lseg = t & 15;          // 16B chunk within 256B row

    const int iters = KTOT / BK;

    #pragma unroll
    for (int i = 0; i < 4; i++)
        #pragma unroll
        for (int j = 0; j < 8; j++)
            #pragma unroll
            for (int q = 0; q < 4; q++) f.acc[i][j][q] = 0.f;

    // stage loader: 24 chunks/thread (j<8 -> A rows 0..127, j>=8 -> B rows 0..255)
    #pragma unroll
    for (int j = 0; j < 24; j++) {
        if (j < 8) {
            const int row = lrow + 16 * j;
            cp16(sb0 + (row * SROW + lseg * 4) * 4,
                 A + (size_t)(m0 + row) * KTOT + lseg * 4);
        } else {
            const int row = lrow + 16 * (j - 8);
            cp16(sb0 + ((BM + row) * SROW + lseg * 4) * 4,
                 B + (size_t)(n0 + row) * KTOT + lseg * 4);
        }
    }
    CP_COMMIT();

    const int wid = t >> 5, lane = t & 31;
    const int wm = wid & 1, wn = wid >> 1;
    const int mrow = wm * 64, nb = wn * 64;

    // ldmatrix per-lane byte offsets (within a stage)
    const uint32_t arow = ((lane >> 3) & 1) * 8 + (lane & 7);
    const uint32_t acol = ((lane >> 4) & 1) * 4;
    const uint32_t a_off = ((mrow + arow) * SROW + acol) * 4;
    const uint32_t brow = ((lane >> 4) & 1) * 8 + (lane & 7);
    const uint32_t bcol = ((lane >> 3) & 1) * 4;
    const uint32_t b_off = ((BM + nb + brow) * SROW + bcol) * 4;

    int rs = 0;
    for (int it = 0; it < iters; it++) {
        CP_WAIT(0);
        __syncthreads();

        if (it + 1 < iters) {
            const int ws = rs ^ 1;
            const int k0 = (it + 1) * BK;
            #pragma unroll
            for (int j = 0; j < 24; j++) {
                if (j < 8) {
                    const int row = lrow + 16 * j;
                    cp16(sb0 + ws * STAGE_BYTES + (row * SROW + lseg * 4) * 4,
                         A + (size_t)(m0 + row) * KTOT + k0 + lseg * 4);
                } else {
                    const int row = lrow + 16 * (j - 8);
                    cp16(sb0 + ws * STAGE_BYTES + ((BM + row) * SROW + lseg * 4) * 4,
                         B + (size_t)(n0 + row) * KTOT + k0 + lseg * 4);
                }
            }
            CP_COMMIT();
        }

        const uint32_t sbase = sb0 + rs * STAGE_BYTES;

        #pragma unroll
        for (int s = 0; s < BK / 8; s++) {
            const uint32_t ko = s * 8 * 4;
            uint32_t a[4][4];
            #pragma unroll
            for (int mt = 0; mt < 4; mt++) {
                ldsm4(a[mt][0], a[mt][1], a[mt][2], a[mt][3],
                      sbase + a_off + mt * 16 * SROW * 4 + ko);
                if (CVTA) {
                    #pragma unroll
                    for (int q = 0; q < 4; q++) a[mt][q] = tf32_rna_bits(a[mt][q]);
                }
            }
            uint32_t b[8][2];
            #pragma unroll
            for (int p = 0; p < 4; p++)
                ldsm4(b[2*p][0], b[2*p][1], b[2*p+1][0], b[2*p+1][1],
                      sbase + b_off + p * 16 * SROW * 4 + ko);
            #pragma unroll
            for (int nt = 0; nt < 8; nt++)
                #pragma unroll
                for (int mt = 0; mt < 4; mt++)
                    mma_tf32(f.acc[mt][nt], a[mt], b[nt][0], b[nt][1]);
        }
        rs ^= 1;
    }
    __syncthreads();
}

// ===========================================================================
// k1: C = x @ Wb^T (interleaved weights, N=1024 stacked). Epilogue:
// z = sigmoid(g)*u, write g_z, per-CTA 128-row tile column sums (128 z-cols).
// A = raw fp32 x (in-register tf32-RNA rounding).
// ===========================================================================
__global__ void __launch_bounds__(256, 1) k1_gemm(const float* __restrict__ x) {
    extern __shared__ char smem[];
    const int n0 = blockIdx.x * BN;
    const int m0 = blockIdx.y * BM;
    Frag f;
    gemm_mainloop<Dn, true>(x, g_wb, m0, n0, smem, f);

    const int t = threadIdx.x;
    const int wid = t >> 5, lane = t & 31;
    const int wm = wid & 1, wn = wid >> 1;
    const int gr = lane >> 2, gc = lane & 3;
    const int zbase = n0 >> 1;             // 128 z-cols per CTA

    float* csum = (float*)smem;
    if (t < 128) csum[t] = 0.f;
    __syncthreads();

    #pragma unroll
    for (int nt = 0; nt < 8; nt++) {
        float cs = 0.f;
        #pragma unroll
        for (int mt = 0; mt < 4; mt++) {
            const int r0 = m0 + wm * 64 + mt * 16 + gr;
            const int zc = zbase + wn * 32 + nt * 4 + gc;
            float z0 = f.acc[mt][nt][1] * sigmoidf_fast(f.acc[mt][nt][0]);
            float z1 = f.acc[mt][nt][3] * sigmoidf_fast(f.acc[mt][nt][2]);
            g_z[(size_t)r0 * SDn + zc] = z0;
            g_z[(size_t)(r0 + 8) * SDn + zc] = z1;
            cs += z0 + z1;
        }
        cs += __shfl_xor_sync(0xffffffffu, cs, 4);
        cs += __shfl_xor_sync(0xffffffffu, cs, 8);
        cs += __shfl_xor_sync(0xffffffffu, cs, 16);
        if (gr == 0)
            atomicAdd(&csum[wn * 32 + nt * 4 + gc], cs);
    }
    __syncthreads();
    if (t < 128)
        g_tilesum[(size_t)blockIdx.y * SDn + zbase + t] = csum[t];
}

// ===========================================================================
// k2: exclusive prefix over tiles per (b,k) channel
// ===========================================================================
__global__ void k2_tileprefix() {
    int idx = blockIdx.x * blockDim.x + threadIdx.x;
    int b = idx / SDn, k = idx % SDn;
    float run = 0.f;
    for (int t = 0; t < NT; t++) {
        size_t off = (size_t)(b * NT + t) * SDn + k;
        float v = g_tilesum[off];
        g_tilesum[off] = run;
        run += v;
    }
}

// ===========================================================================
// k3a: in-tile scan + /denom, rewrite g_z with tf32-rna(h), per-row rms_inv
// ===========================================================================
__global__ void __launch_bounds__(512) k3a_scan() {
    const int mt = blockIdx.x;
    const int t = mt & (NT - 1);
    const int k = threadIdx.x;
    const int warp = k >> 5, lane = k & 31;
    const int base = mt * TS;

    __shared__ float ssp[TS][16];

    float carry = g_tilesum[(size_t)mt * SDn + k];

    #pragma unroll 4
    for (int r = 0; r < TS; r++) {
        const size_t off = (size_t)(base + r) * SDn + k;
        carry += g_z[off];
        float h = __fdividef(carry, (float)(t * TS + r + 1));
        h = tf32_rna(h);
        g_z[off] = h;
        float sq = h * h;
        #pragma unroll
        for (int o = 16; o > 0; o >>= 1) sq += __shfl_xor_sync(0xffffffffu, sq, o);
        if (lane == 0) ssp[r][warp] = sq;
    }
    __syncthreads();
    if (k < TS) {
        float s = 0.f;
        #pragma unroll
        for (int w = 0; w < 16; w++) s += ssp[k][w];
        g_rmsinv[base + k] = rsqrtf(s * (1.0f / SDn) + RMS_EPS);
    }
}

// ===========================================================================
// k3b: out = rms_inv[m] * (h @ Wo^T), M=32768, N=1024, K=512
// ===========================================================================
__global__ void __launch_bounds__(256, 1) k3b_gemm(float* __restrict__ out) {
    extern __shared__ char smem[];
    const int n0 = blockIdx.x * BN;
    const int m0 = blockIdx.y * BM;
    Frag f;
    gemm_mainloop<SDn, false>(g_z, g_wo, m0, n0, smem, f);

    const int t = threadIdx.x;
    const int wid = t >> 5, lane = t & 31;
    const int wm = wid & 1, wn = wid >> 1;
    const int gr = lane >> 2, gc = lane & 3;

    #pragma unroll
    for (int mt = 0; mt < 4; mt++) {
        const int r0 = m0 + wm * 64 + mt * 16 + gr;
        const float ri0 = g_rmsinv[r0];
        const float ri1 = g_rmsinv[r0 + 8];
        #pragma unroll
        for (int nt = 0; nt < 8; nt++) {
            const int col = n0 + wn * 64 + nt * 8 + gc * 2;
            float2 v0 = { f.acc[mt][nt][0] * ri0, f.acc[mt][nt][1] * ri0 };
            float2 v1 = { f.acc[mt][nt][2] * ri1, f.acc[mt][nt][3] * ri1 };
            *(float2*)&out[(size_t)r0 * Dn + col] = v0;
            *(float2*)&out[(size_t)(r0 + 8) * Dn + col] = v1;
        }
    }
}

// ===========================================================================
// host side
// ===========================================================================
extern "C" void kernel_launch(void* const* d_in, const int* in_sizes, int n_in,
                              void* d_out, int out_size) {
    const float* x  = (const float*)d_in[0];
    const float* Wu = (const float*)d_in[1];
    const float* Wg = (const float*)d_in[2];
    const float* Wo = (const float*)d_in[3];
    float* out = (float*)d_out;

    void *pwb, *pwo;
    cudaGetSymbolAddress(&pwb, g_wb);
    cudaGetSymbolAddress(&pwo, g_wo);

    cudaFuncSetAttribute(k1_gemm,  cudaFuncAttributeMaxDynamicSharedMemorySize, SMEM_BYTES);
    cudaFuncSetAttribute(k3b_gemm, cudaFuncAttributeMaxDynamicSharedMemorySize, SMEM_BYTES);

    k_cvt_pair<<<512, 256>>>((const float4*)Wg, (const float4*)Wu, (float4*)pwb);
    k_cvt<<<512, 256>>>((const float4*)Wo, (float4*)pwo, Dn * SDn / 4);

    k1_gemm<<<dim3(2 * SDn / BN, Mn / BM), 256, SMEM_BYTES>>>(x);
    k2_tileprefix<<<(Bn * SDn) / 256, 256>>>();
    k3a_scan<<<Mn / TS, 512>>>();
    k3b_gemm<<<dim3(Dn / BN, Mn / BM), 256, SMEM_BYTES>>>(out);
}

// round 8
// speedup vs baseline: 1.9304x; 1.4879x over previous
#include <cuda_runtime.h>
#include <cuda_fp16.h>
#include <cstdint>
#include <math.h>

// ---------------- problem constants ----------------
#define Bn  4
#define Sn  8192
#define Dn  1024
#define SDn 512
#define Mn  (Bn * Sn)          // 32768 rows
#define TS  128                // scan tile (rows) == BM
#define NT  (Sn / TS)          // 64 tiles per batch
#define RMS_EPS 1.1920929e-07f

// ---------------- GEMM tiling (fp16 operands) ----------------
#define BM 128
#define BN 256
#define BKH 64                               // K halves per stage (128 B rows)
#define STAGES 4
#define SROWH 72                             // padded halves per row (64+8) -> 144 B
#define ROWB (SROWH * 2)                     // 144 bytes
#define STAGE_BYTES ((BM + BN) * ROWB)       // 55296 B
#define SMEM_BYTES  (STAGES * STAGE_BYTES)   // 221184 B

// ---------------- scratch ----------------
__device__ __align__(128) __half g_xh[Mn * Dn];       // x, fp16
__device__ __align__(128) __half g_wb[2 * SDn * Dn];  // interleaved Wg/Wu rows, fp16
__device__ __align__(128) __half g_wo[Dn * SDn];      // W_out fp16
__device__ __align__(128) float  g_z[Mn * SDn];       // z (fp32, scan input)
__device__ __align__(128) __half g_h[Mn * SDn];       // h (fp16, k3b input)
__device__ __align__(128) float  g_tilesum[(Mn / TS) * SDn];
__device__ __align__(128) float  g_rmsinv[Mn];

// ---------------- helpers ----------------
__device__ __forceinline__ uint32_t smem_u32(const void* p) {
    uint32_t a;
    asm("{ .reg .u64 t; cvta.to.shared.u64 t, %1; cvt.u32.u64 %0, t; }" : "=r"(a) : "l"(p));
    return a;
}
__device__ __forceinline__ void cp16(uint32_t d, const void* s) {
    asm volatile("cp.async.cg.shared.global [%0], [%1], 16;" :: "r"(d), "l"(s));
}
#define CP_COMMIT() asm volatile("cp.async.commit_group;" ::: "memory")
#define CP_WAIT(n)  asm volatile("cp.async.wait_group %0;" :: "n"(n) : "memory")

__device__ __forceinline__ void mma_f16(float* c, const uint32_t* a, uint32_t b0, uint32_t b1) {
    asm volatile(
        "mma.sync.aligned.m16n8k16.row.col.f32.f16.f16.f32 "
        "{%0,%1,%2,%3}, {%4,%5,%6,%7}, {%8,%9}, {%0,%1,%2,%3};"
        : "+f"(c[0]), "+f"(c[1]), "+f"(c[2]), "+f"(c[3])
        : "r"(a[0]), "r"(a[1]), "r"(a[2]), "r"(a[3]), "r"(b0), "r"(b1));
}
__device__ __forceinline__ void ldsm4(uint32_t& r0, uint32_t& r1, uint32_t& r2, uint32_t& r3,
                                      uint32_t addr) {
    asm volatile("ldmatrix.sync.aligned.m8n8.x4.shared.b16 {%0,%1,%2,%3}, [%4];"
        : "=r"(r0), "=r"(r1), "=r"(r2), "=r"(r3) : "r"(addr));
}
__device__ __forceinline__ float sigmoidf_fast(float g) {
    return 1.0f / (1.0f + __expf(-g));
}

// ===========================================================================
// conversion kernels: fp32 -> fp16 (RN)
// ===========================================================================
__global__ void k_cvt_h(const float4* __restrict__ src, __half2* __restrict__ dst, int n4) {
    for (int i = blockIdx.x * blockDim.x + threadIdx.x; i < n4; i += gridDim.x * blockDim.x) {
        float4 v = src[i];
        dst[2 * i]     = __floats2half2_rn(v.x, v.y);
        dst[2 * i + 1] = __floats2half2_rn(v.z, v.w);
    }
}
// interleave: dst row 2i <- Wg row i, dst row 2i+1 <- Wu row i (rows of Dn)
__global__ void k_cvt_pair_h(const float4* __restrict__ wg, const float4* __restrict__ wu,
                             __half2* __restrict__ dst) {
    const int RW = Dn / 4;                       // float4 per row
    const int total = SDn * RW;
    for (int i = blockIdx.x * blockDim.x + threadIdx.x; i < total; i += gridDim.x * blockDim.x) {
        int r = i / RW, c = i % RW;
        float4 vg = wg[i];
        float4 vu = wu[i];
        size_t dg = (size_t)(2 * r) * (Dn / 2) + 2 * c;
        size_t du = (size_t)(2 * r + 1) * (Dn / 2) + 2 * c;
        dst[dg]     = __floats2half2_rn(vg.x, vg.y);
        dst[dg + 1] = __floats2half2_rn(vg.z, vg.w);
        dst[du]     = __floats2half2_rn(vu.x, vu.y);
        dst[du + 1] = __floats2half2_rn(vu.z, vu.w);
    }
}

// ===========================================================================
// fp16 GEMM mainloop. A: [M x K] rm halves, B: [N x K] rm halves (C = A@B^T).
// CTA tile 128x256, 256 threads, warp grid 2(M) x 4(N), warp tile 64x64.
// BKH=64 halves/stage, 4 stages, m16n8k16: per k16-step 8 ldsm.x4 -> 32 MMAs.
// ===========================================================================
struct Frag { float acc[4][8][4]; };

template<int KTOT>
__device__ __forceinline__ void gemm_mainloop(const __half* __restrict__ A,
                                              const __half* __restrict__ B,
                                              int m0, int n0, char* smem, Frag& f) {
    const int t = threadIdx.x;
    const uint32_t sb0 = smem_u32(smem);
    const int lrow = t >> 3;          // 0..31
    const int lseg = t & 7;           // 16B chunk (8 halves) within 128B row

    const int iters = KTOT / BKH;

    #pragma unroll
    for (int i = 0; i < 4; i++)
        #pragma unroll
        for (int j = 0; j < 8; j++)
            #pragma unroll
            for (int q = 0; q < 4; q++) f.acc[i][j][q] = 0.f;

    // stage loader: 12 chunks/thread (i<4 -> A rows 0..127, i>=4 -> B rows 0..255)
    #pragma unroll
    for (int p = 0; p < STAGES - 1; p++) {
        const int k0 = p * BKH;
        #pragma unroll
        for (int i = 0; i < 12; i++) {
            if (i < 4) {
                const int row = 32 * i + lrow;
                cp16(sb0 + p * STAGE_BYTES + row * ROWB + lseg * 16,
                     A + (size_t)(m0 + row) * KTOT + k0 + lseg * 8);
            } else {
                const int row = 32 * (i - 4) + lrow;
                cp16(sb0 + p * STAGE_BYTES + (BM + row) * ROWB + lseg * 16,
                     B + (size_t)(n0 + row) * KTOT + k0 + lseg * 8);
            }
        }
        CP_COMMIT();
    }

    const int wid = t >> 5, lane = t & 31;
    const int wm = wid & 1, wn = wid >> 1;
    const int mrow = wm * 64, nb = wn * 64;

    // ldmatrix per-lane byte offsets (within a stage)
    const uint32_t arow = ((lane >> 3) & 1) * 8 + (lane & 7);
    const uint32_t acolb = ((lane >> 4) & 1) * 16;
    const uint32_t a_off = (mrow + arow) * ROWB + acolb;
    const uint32_t brow = ((lane >> 4) & 1) * 8 + (lane & 7);
    const uint32_t bcolb = ((lane >> 3) & 1) * 16;
    const uint32_t b_off = (BM + nb + brow) * ROWB + bcolb;

    int rs = 0;
    for (int it = 0; it < iters; it++) {
        CP_WAIT(STAGES - 2);
        __syncthreads();

        if (it + STAGES - 1 < iters) {
            int ws = rs + STAGES - 1; if (ws >= STAGES) ws -= STAGES;
            const int k0 = (it + STAGES - 1) * BKH;
            #pragma unroll
            for (int i = 0; i < 12; i++) {
                if (i < 4) {
                    const int row = 32 * i + lrow;
                    cp16(sb0 + ws * STAGE_BYTES + row * ROWB + lseg * 16,
                         A + (size_t)(m0 + row) * KTOT + k0 + lseg * 8);
                } else {
                    const int row = 32 * (i - 4) + lrow;
                    cp16(sb0 + ws * STAGE_BYTES + (BM + row) * ROWB + lseg * 16,
                         B + (size_t)(n0 + row) * KTOT + k0 + lseg * 8);
                }
            }
        }
        CP_COMMIT();

        const uint32_t sbase = sb0 + rs * STAGE_BYTES;

        #pragma unroll
        for (int s = 0; s < BKH / 16; s++) {      // 4 k16-steps
            const uint32_t ko = s * 32;           // 16 halves = 32 bytes
            uint32_t a[4][4];
            #pragma unroll
            for (int mt = 0; mt < 4; mt++)
                ldsm4(a[mt][0], a[mt][1], a[mt][2], a[mt][3],
                      sbase + a_off + mt * 16 * ROWB + ko);
            uint32_t b[8][2];
            #pragma unroll
            for (int p = 0; p < 4; p++)
                ldsm4(b[2*p][0], b[2*p][1], b[2*p+1][0], b[2*p+1][1],
                      sbase + b_off + p * 16 * ROWB + ko);
            #pragma unroll
            for (int nt = 0; nt < 8; nt++)
                #pragma unroll
                for (int mt = 0; mt < 4; mt++)
                    mma_f16(f.acc[mt][nt], a[mt], b[nt][0], b[nt][1]);
        }
        rs++; if (rs == STAGES) rs = 0;
    }
    __syncthreads();
}

// ===========================================================================
// k1: C = x @ Wb^T (interleaved weights, stacked N=1024). Epilogue:
// z = sigmoid(g)*u (fp32), write g_z, per-CTA 128-row tile column sums.
// ===========================================================================
__global__ void __launch_bounds__(256, 1) k1_gemm() {
    extern __shared__ char smem[];
    const int n0 = blockIdx.x * BN;
    const int m0 = blockIdx.y * BM;
    Frag f;
    gemm_mainloop<Dn>(g_xh, g_wb, m0, n0, smem, f);

    const int t = threadIdx.x;
    const int wid = t >> 5, lane = t & 31;
    const int wm = wid & 1, wn = wid >> 1;
    const int gr = lane >> 2, gc = lane & 3;
    const int zbase = n0 >> 1;             // 128 z-cols per CTA

    float* csum = (float*)smem;
    if (t < 128) csum[t] = 0.f;
    __syncthreads();

    #pragma unroll
    for (int nt = 0; nt < 8; nt++) {
        float cs = 0.f;
        #pragma unroll
        for (int mt = 0; mt < 4; mt++) {
            const int r0 = m0 + wm * 64 + mt * 16 + gr;
            const int zc = zbase + wn * 32 + nt * 4 + gc;
            float z0 = f.acc[mt][nt][1] * sigmoidf_fast(f.acc[mt][nt][0]);
            float z1 = f.acc[mt][nt][3] * sigmoidf_fast(f.acc[mt][nt][2]);
            g_z[(size_t)r0 * SDn + zc] = z0;
            g_z[(size_t)(r0 + 8) * SDn + zc] = z1;
            cs += z0 + z1;
        }
        cs += __shfl_xor_sync(0xffffffffu, cs, 4);
        cs += __shfl_xor_sync(0xffffffffu, cs, 8);
        cs += __shfl_xor_sync(0xffffffffu, cs, 16);
        if (gr == 0)
            atomicAdd(&csum[wn * 32 + nt * 4 + gc], cs);
    }
    __syncthreads();
    if (t < 128)
        g_tilesum[(size_t)blockIdx.y * SDn + zbase + t] = csum[t];
}

// ===========================================================================
// k2: exclusive prefix over tiles per (b,k) channel (register-batched loads)
// ===========================================================================
__global__ void k2_tileprefix() {
    const int idx = blockIdx.x * blockDim.x + threadIdx.x;   // 0..2047
    const size_t base = (size_t)(idx / SDn) * NT * SDn + (idx % SDn);
    float v[NT];
    #pragma unroll
    for (int t = 0; t < NT; t++) v[t] = g_tilesum[base + (size_t)t * SDn];
    float run = 0.f;
    #pragma unroll
    for (int t = 0; t < NT; t++) {
        float nv = run + v[t];
        g_tilesum[base + (size_t)t * SDn] = run;
        run = nv;
    }
}

// ===========================================================================
// k3a: in-tile scan + /denom; write h as fp16 to g_h; per-row rms_inv
// ===========================================================================
__global__ void __launch_bounds__(512) k3a_scan() {
    const int mt = blockIdx.x;
    const int t = mt & (NT - 1);
    const int k = threadIdx.x;
    const int warp = k >> 5, lane = k & 31;
    const int base = mt * TS;

    __shared__ float ssp[TS][16];

    float carry = g_tilesum[(size_t)mt * SDn + k];

    #pragma unroll 4
    for (int r = 0; r < TS; r++) {
        const size_t off = (size_t)(base + r) * SDn + k;
        carry += g_z[off];
        float h = __fdividef(carry, (float)(t * TS + r + 1));
        __half hh = __float2half_rn(h);
        g_h[off] = hh;
        float hr = __half2float(hh);
        float sq = hr * hr;
        #pragma unroll
        for (int o = 16; o > 0; o >>= 1) sq += __shfl_xor_sync(0xffffffffu, sq, o);
        if (lane == 0) ssp[r][warp] = sq;
    }
    __syncthreads();
    if (k < TS) {
        float s = 0.f;
        #pragma unroll
        for (int w = 0; w < 16; w++) s += ssp[k][w];
        g_rmsinv[base + k] = rsqrtf(s * (1.0f / SDn) + RMS_EPS);
    }
}

// ===========================================================================
// k3b: out = rms_inv[m] * (h @ Wo^T), M=32768, N=1024, K=512 (fp16 inputs)
// ===========================================================================
__global__ void __launch_bounds__(256, 1) k3b_gemm(float* __restrict__ out) {
    extern __shared__ char smem[];
    const int n0 = blockIdx.x * BN;
    const int m0 = blockIdx.y * BM;
    Frag f;
    gemm_mainloop<SDn>(g_h, g_wo, m0, n0, smem, f);

    const int t = threadIdx.x;
    const int wid = t >> 5, lane = t & 31;
    const int wm = wid & 1, wn = wid >> 1;
    const int gr = lane >> 2, gc = lane & 3;

    #pragma unroll
    for (int mt = 0; mt < 4; mt++) {
        const int r0 = m0 + wm * 64 + mt * 16 + gr;
        const float ri0 = g_rmsinv[r0];
        const float ri1 = g_rmsinv[r0 + 8];
        #pragma unroll
        for (int nt = 0; nt < 8; nt++) {
            const int col = n0 + wn * 64 + nt * 8 + gc * 2;
            float2 v0 = { f.acc[mt][nt][0] * ri0, f.acc[mt][nt][1] * ri0 };
            float2 v1 = { f.acc[mt][nt][2] * ri1, f.acc[mt][nt][3] * ri1 };
            *(float2*)&out[(size_t)r0 * Dn + col] = v0;
            *(float2*)&out[(size_t)(r0 + 8) * Dn + col] = v1;
        }
    }
}

// ===========================================================================
// host side
// ===========================================================================
extern "C" void kernel_launch(void* const* d_in, const int* in_sizes, int n_in,
                              void* d_out, int out_size) {
    const float* x  = (const float*)d_in[0];
    const float* Wu = (const float*)d_in[1];
    const float* Wg = (const float*)d_in[2];
    const float* Wo = (const float*)d_in[3];
    float* out = (float*)d_out;

    void *pxh, *pwb, *pwo;
    cudaGetSymbolAddress(&pxh, g_xh);
    cudaGetSymbolAddress(&pwb, g_wb);
    cudaGetSymbolAddress(&pwo, g_wo);

    cudaFuncSetAttribute(k1_gemm,  cudaFuncAttributeMaxDynamicSharedMemorySize, SMEM_BYTES);
    cudaFuncSetAttribute(k3b_gemm, cudaFuncAttributeMaxDynamicSharedMemorySize, SMEM_BYTES);

    k_cvt_h<<<4096, 256>>>((const float4*)x, (__half2*)pxh, Mn * Dn / 4);
    k_cvt_pair_h<<<512, 256>>>((const float4*)Wg, (const float4*)Wu, (__half2*)pwb);
    k_cvt_h<<<512, 256>>>((const float4*)Wo, (__half2*)pwo, Dn * SDn / 4);

    k1_gemm<<<dim3(2 * SDn / BN, Mn / BM), 256, SMEM_BYTES>>>();
    k2_tileprefix<<<(Bn * SDn) / 256, 256>>>();
    k3a_scan<<<Mn / TS, 512>>>();
    k3b_gemm<<<dim3(Dn / BN, Mn / BM), 256, SMEM_BYTES>>>(out);
}

// round 9
// speedup vs baseline: 1.9331x; 1.0014x over previous
#include <cuda_runtime.h>
#include <cuda_fp16.h>
#include <cstdint>
#include <math.h>

// ---------------- problem constants ----------------
#define Bn  4
#define Sn  8192
#define Dn  1024
#define SDn 512
#define Mn  (Bn * Sn)          // 32768 rows
#define TS  128                // scan tile (rows) == BM
#define NT  (Sn / TS)          // 64 tiles per batch
#define RMS_EPS 1.1920929e-07f

// ---------------- GEMM tiling (fp16 operands) ----------------
#define BM 128
#define BN 256
#define BKH 64                               // K halves per stage (128 B rows)
#define STAGES 4
#define SROWH 72                             // padded halves per row (64+8) -> 144 B
#define ROWB (SROWH * 2)                     // 144 bytes
#define STAGE_BYTES ((BM + BN) * ROWB)       // 55296 B
#define SMEM_BYTES  (STAGES * STAGE_BYTES)   // 221184 B

// ---------------- scratch ----------------
__device__ __align__(128) __half g_xh[Mn * Dn];       // x, fp16
__device__ __align__(128) __half g_wb[2 * SDn * Dn];  // interleaved Wg/Wu rows, fp16
__device__ __align__(128) __half g_wo[Dn * SDn];      // W_out fp16
__device__ __align__(128) float  g_z[Mn * SDn];       // z (fp32, scan input)
__device__ __align__(128) __half g_h[Mn * SDn];       // h (fp16, k3b input)
__device__ __align__(128) float  g_tilesum[(Mn / TS) * SDn];
__device__ __align__(128) float  g_rmsinv[Mn];

// ---------------- helpers ----------------
__device__ __forceinline__ uint32_t smem_u32(const void* p) {
    uint32_t a;
    asm("{ .reg .u64 t; cvta.to.shared.u64 t, %1; cvt.u32.u64 %0, t; }" : "=r"(a) : "l"(p));
    return a;
}
__device__ __forceinline__ void cp16(uint32_t d, const void* s) {
    asm volatile("cp.async.cg.shared.global [%0], [%1], 16;" :: "r"(d), "l"(s));
}
#define CP_COMMIT() asm volatile("cp.async.commit_group;" ::: "memory")
#define CP_WAIT(n)  asm volatile("cp.async.wait_group %0;" :: "n"(n) : "memory")

__device__ __forceinline__ void mma_f16(float* c, const uint32_t* a, uint32_t b0, uint32_t b1) {
    asm volatile(
        "mma.sync.aligned.m16n8k16.row.col.f32.f16.f16.f32 "
        "{%0,%1,%2,%3}, {%4,%5,%6,%7}, {%8,%9}, {%0,%1,%2,%3};"
        : "+f"(c[0]), "+f"(c[1]), "+f"(c[2]), "+f"(c[3])
        : "r"(a[0]), "r"(a[1]), "r"(a[2]), "r"(a[3]), "r"(b0), "r"(b1));
}
__device__ __forceinline__ void ldsm4(uint32_t& r0, uint32_t& r1, uint32_t& r2, uint32_t& r3,
                                      uint32_t addr) {
    asm volatile("ldmatrix.sync.aligned.m8n8.x4.shared.b16 {%0,%1,%2,%3}, [%4];"
        : "=r"(r0), "=r"(r1), "=r"(r2), "=r"(r3) : "r"(addr));
}
__device__ __forceinline__ float sigmoidf_fast(float g) {
    return 1.0f / (1.0f + __expf(-g));
}

// ===========================================================================
// conversion kernels: fp32 -> fp16 (RN)
// ===========================================================================
__global__ void k_cvt_h(const float4* __restrict__ src, __half2* __restrict__ dst, int n4) {
    for (int i = blockIdx.x * blockDim.x + threadIdx.x; i < n4; i += gridDim.x * blockDim.x) {
        float4 v = src[i];
        dst[2 * i]     = __floats2half2_rn(v.x, v.y);
        dst[2 * i + 1] = __floats2half2_rn(v.z, v.w);
    }
}
__global__ void k_cvt_pair_h(const float4* __restrict__ wg, const float4* __restrict__ wu,
                             __half2* __restrict__ dst) {
    const int RW = Dn / 4;
    const int total = SDn * RW;
    for (int i = blockIdx.x * blockDim.x + threadIdx.x; i < total; i += gridDim.x * blockDim.x) {
        int r = i / RW, c = i % RW;
        float4 vg = wg[i];
        float4 vu = wu[i];
        size_t dg = (size_t)(2 * r) * (Dn / 2) + 2 * c;
        size_t du = (size_t)(2 * r + 1) * (Dn / 2) + 2 * c;
        dst[dg]     = __floats2half2_rn(vg.x, vg.y);
        dst[dg + 1] = __floats2half2_rn(vg.z, vg.w);
        dst[du]     = __floats2half2_rn(vu.x, vu.y);
        dst[du + 1] = __floats2half2_rn(vu.z, vu.w);
    }
}

// ===========================================================================
// fp16 GEMM mainloop, fragment double-buffered across k16 steps.
// A: [M x K] rm halves, B: [N x K] rm halves (C = A@B^T). CTA 128x256,
// 256 threads, warp grid 2(M) x 4(N), warp tile 64x64.
// ===========================================================================
struct Frag { float acc[4][8][4]; };

template<int KTOT>
__device__ __forceinline__ void gemm_mainloop(const __half* __restrict__ A,
                                              const __half* __restrict__ B,
                                              int m0, int n0, char* smem, Frag& f) {
    const int t = threadIdx.x;
    const uint32_t sb0 = smem_u32(smem);
    const int lrow = t >> 3;          // 0..31
    const int lseg = t & 7;           // 16B chunk (8 halves) within 128B row

    const int iters = KTOT / BKH;

    #pragma unroll
    for (int i = 0; i < 4; i++)
        #pragma unroll
        for (int j = 0; j < 8; j++)
            #pragma unroll
            for (int q = 0; q < 4; q++) f.acc[i][j][q] = 0.f;

    #pragma unroll
    for (int p = 0; p < STAGES - 1; p++) {
        const int k0 = p * BKH;
        #pragma unroll
        for (int i = 0; i < 12; i++) {
            if (i < 4) {
                const int row = 32 * i + lrow;
                cp16(sb0 + p * STAGE_BYTES + row * ROWB + lseg * 16,
                     A + (size_t)(m0 + row) * KTOT + k0 + lseg * 8);
            } else {
                const int row = 32 * (i - 4) + lrow;
                cp16(sb0 + p * STAGE_BYTES + (BM + row) * ROWB + lseg * 16,
                     B + (size_t)(n0 + row) * KTOT + k0 + lseg * 8);
            }
        }
        CP_COMMIT();
    }

    const int wid = t >> 5, lane = t & 31;
    const int wm = wid & 1, wn = wid >> 1;
    const int mrow = wm * 64, nb = wn * 64;

    const uint32_t arow = ((lane >> 3) & 1) * 8 + (lane & 7);
    const uint32_t acolb = ((lane >> 4) & 1) * 16;
    const uint32_t a_off = (mrow + arow) * ROWB + acolb;
    const uint32_t brow = ((lane >> 4) & 1) * 8 + (lane & 7);
    const uint32_t bcolb = ((lane >> 3) & 1) * 16;
    const uint32_t b_off = (BM + nb + brow) * ROWB + bcolb;

    uint32_t a[2][4][4];     // [buf][mt][4]
    uint32_t b[2][8][2];     // [buf][nt][2]

    int rs = 0;
    for (int it = 0; it < iters; it++) {
        CP_WAIT(STAGES - 2);
        __syncthreads();

        if (it + STAGES - 1 < iters) {
            int ws = rs + STAGES - 1; if (ws >= STAGES) ws -= STAGES;
            const int k0 = (it + STAGES - 1) * BKH;
            #pragma unroll
            for (int i = 0; i < 12; i++) {
                if (i < 4) {
                    const int row = 32 * i + lrow;
                    cp16(sb0 + ws * STAGE_BYTES + row * ROWB + lseg * 16,
                         A + (size_t)(m0 + row) * KTOT + k0 + lseg * 8);
                } else {
                    const int row = 32 * (i - 4) + lrow;
                    cp16(sb0 + ws * STAGE_BYTES + (BM + row) * ROWB + lseg * 16,
                         B + (size_t)(n0 + row) * KTOT + k0 + lseg * 8);
                }
            }
        }
        CP_COMMIT();

        const uint32_t sbase = sb0 + rs * STAGE_BYTES;

        // prefetch fragments for k16-step 0 into buf 0
        #pragma unroll
        for (int mt = 0; mt < 4; mt++)
            ldsm4(a[0][mt][0], a[0][mt][1], a[0][mt][2], a[0][mt][3],
                  sbase + a_off + mt * 16 * ROWB);
        #pragma unroll
        for (int p = 0; p < 4; p++)
            ldsm4(b[0][2*p][0], b[0][2*p][1], b[0][2*p+1][0], b[0][2*p+1][1],
                  sbase + b_off + p * 16 * ROWB);

        #pragma unroll
        for (int s = 0; s < BKH / 16; s++) {      // 4 k16-steps
            const int cur = s & 1, nxt = cur ^ 1;
            if (s < BKH / 16 - 1) {               // prefetch next step's frags
                const uint32_t ko = (s + 1) * 32;
                #pragma unroll
                for (int mt = 0; mt < 4; mt++)
                    ldsm4(a[nxt][mt][0], a[nxt][mt][1], a[nxt][mt][2], a[nxt][mt][3],
                          sbase + a_off + mt * 16 * ROWB + ko);
                #pragma unroll
                for (int p = 0; p < 4; p++)
                    ldsm4(b[nxt][2*p][0], b[nxt][2*p][1], b[nxt][2*p+1][0], b[nxt][2*p+1][1],
                          sbase + b_off + p * 16 * ROWB + ko);
            }
            #pragma unroll
            for (int nt = 0; nt < 8; nt++)
                #pragma unroll
                for (int mt = 0; mt < 4; mt++)
                    mma_f16(f.acc[mt][nt], a[cur][mt], b[cur][nt][0], b[cur][nt][1]);
        }
        rs++; if (rs == STAGES) rs = 0;
    }
    __syncthreads();
}

// ===========================================================================
// k1: C = x @ Wb^T (interleaved weights, stacked N=1024). Epilogue:
// z = sigmoid(g)*u (fp32), write g_z, per-CTA 128-row tile column sums.
// ===========================================================================
__global__ void __launch_bounds__(256, 1) k1_gemm() {
    extern __shared__ char smem[];
    const int n0 = blockIdx.x * BN;
    const int m0 = blockIdx.y * BM;
    Frag f;
    gemm_mainloop<Dn>(g_xh, g_wb, m0, n0, smem, f);

    const int t = threadIdx.x;
    const int wid = t >> 5, lane = t & 31;
    const int wm = wid & 1, wn = wid >> 1;
    const int gr = lane >> 2, gc = lane & 3;
    const int zbase = n0 >> 1;

    float* csum = (float*)smem;
    if (t < 128) csum[t] = 0.f;
    __syncthreads();

    #pragma unroll
    for (int nt = 0; nt < 8; nt++) {
        float cs = 0.f;
        #pragma unroll
        for (int mt = 0; mt < 4; mt++) {
            const int r0 = m0 + wm * 64 + mt * 16 + gr;
            const int zc = zbase + wn * 32 + nt * 4 + gc;
            float z0 = f.acc[mt][nt][1] * sigmoidf_fast(f.acc[mt][nt][0]);
            float z1 = f.acc[mt][nt][3] * sigmoidf_fast(f.acc[mt][nt][2]);
            g_z[(size_t)r0 * SDn + zc] = z0;
            g_z[(size_t)(r0 + 8) * SDn + zc] = z1;
            cs += z0 + z1;
        }
        cs += __shfl_xor_sync(0xffffffffu, cs, 4);
        cs += __shfl_xor_sync(0xffffffffu, cs, 8);
        cs += __shfl_xor_sync(0xffffffffu, cs, 16);
        if (gr == 0)
            atomicAdd(&csum[wn * 32 + nt * 4 + gc], cs);
    }
    __syncthreads();
    if (t < 128)
        g_tilesum[(size_t)blockIdx.y * SDn + zbase + t] = csum[t];
}

// ===========================================================================
// k2: exclusive prefix over tiles per (b,k) channel (register-batched loads)
// ===========================================================================
__global__ void k2_tileprefix() {
    const int idx = blockIdx.x * blockDim.x + threadIdx.x;
    const size_t base = (size_t)(idx / SDn) * NT * SDn + (idx % SDn);
    float v[NT];
    #pragma unroll
    for (int t = 0; t < NT; t++) v[t] = g_tilesum[base + (size_t)t * SDn];
    float run = 0.f;
    #pragma unroll
    for (int t = 0; t < NT; t++) {
        float nv = run + v[t];
        g_tilesum[base + (size_t)t * SDn] = run;
        run = nv;
    }
}

// ===========================================================================
// k3a: in-tile scan + /denom; write h as fp16 to g_h; per-row rms_inv
// ===========================================================================
__global__ void __launch_bounds__(512) k3a_scan() {
    const int mt = blockIdx.x;
    const int t = mt & (NT - 1);
    const int k = threadIdx.x;
    const int warp = k >> 5, lane = k & 31;
    const int base = mt * TS;

    __shared__ float ssp[TS][16];

    float carry = g_tilesum[(size_t)mt * SDn + k];

    #pragma unroll 4
    for (int r = 0; r < TS; r++) {
        const size_t off = (size_t)(base + r) * SDn + k;
        carry += g_z[off];
        float h = __fdividef(carry, (float)(t * TS + r + 1));
        __half hh = __float2half_rn(h);
        g_h[off] = hh;
        float hr = __half2float(hh);
        float sq = hr * hr;
        #pragma unroll
        for (int o = 16; o > 0; o >>= 1) sq += __shfl_xor_sync(0xffffffffu, sq, o);
        if (lane == 0) ssp[r][warp] = sq;
    }
    __syncthreads();
    if (k < TS) {
        float s = 0.f;
        #pragma unroll
        for (int w = 0; w < 16; w++) s += ssp[k][w];
        g_rmsinv[base + k] = rsqrtf(s * (1.0f / SDn) + RMS_EPS);
    }
}

// ===========================================================================
// k3b: out = rms_inv[m] * (h @ Wo^T), M=32768, N=1024, K=512 (fp16 inputs)
// ===========================================================================
__global__ void __launch_bounds__(256, 1) k3b_gemm(float* __restrict__ out) {
    extern __shared__ char smem[];
    const int n0 = blockIdx.x * BN;
    const int m0 = blockIdx.y * BM;
    Frag f;
    gemm_mainloop<SDn>(g_h, g_wo, m0, n0, smem, f);

    const int t = threadIdx.x;
    const int wid = t >> 5, lane = t & 31;
    const int wm = wid & 1, wn = wid >> 1;
    const int gr = lane >> 2, gc = lane & 3;

    #pragma unroll
    for (int mt = 0; mt < 4; mt++) {
        const int r0 = m0 + wm * 64 + mt * 16 + gr;
        const float ri0 = g_rmsinv[r0];
        const float ri1 = g_rmsinv[r0 + 8];
        #pragma unroll
        for (int nt = 0; nt < 8; nt++) {
            const int col = n0 + wn * 64 + nt * 8 + gc * 2;
            float2 v0 = { f.acc[mt][nt][0] * ri0, f.acc[mt][nt][1] * ri0 };
            float2 v1 = { f.acc[mt][nt][2] * ri1, f.acc[mt][nt][3] * ri1 };
            *(float2*)&out[(size_t)r0 * Dn + col] = v0;
            *(float2*)&out[(size_t)(r0 + 8) * Dn + col] = v1;
        }
    }
}

// ===========================================================================
// host side
// ===========================================================================
extern "C" void kernel_launch(void* const* d_in, const int* in_sizes, int n_in,
                              void* d_out, int out_size) {
    const float* x  = (const float*)d_in[0];
    const float* Wu = (const float*)d_in[1];
    const float* Wg = (const float*)d_in[2];
    const float* Wo = (const float*)d_in[3];
    float* out = (float*)d_out;

    void *pxh, *pwb, *pwo;
    cudaGetSymbolAddress(&pxh, g_xh);
    cudaGetSymbolAddress(&pwb, g_wb);
    cudaGetSymbolAddress(&pwo, g_wo);

    cudaFuncSetAttribute(k1_gemm,  cudaFuncAttributeMaxDynamicSharedMemorySize, SMEM_BYTES);
    cudaFuncSetAttribute(k3b_gemm, cudaFuncAttributeMaxDynamicSharedMemorySize, SMEM_BYTES);

    k_cvt_h<<<4096, 256>>>((const float4*)x, (__half2*)pxh, Mn * Dn / 4);
    k_cvt_pair_h<<<512, 256>>>((const float4*)Wg, (const float4*)Wu, (__half2*)pwb);
    k_cvt_h<<<512, 256>>>((const float4*)Wo, (__half2*)pwo, Dn * SDn / 4);

    k1_gemm<<<dim3(2 * SDn / BN, Mn / BM), 256, SMEM_BYTES>>>();
    k2_tileprefix<<<(Bn * SDn) / 256, 256>>>();
    k3a_scan<<<Mn / TS, 512>>>();
    k3b_gemm<<<dim3(Dn / BN, Mn / BM), 256, SMEM_BYTES>>>(out);
}

// round 10
// speedup vs baseline: 1.9913x; 1.0301x over previous
#include <cuda_runtime.h>
#include <cuda_fp16.h>
#include <cstdint>
#include <math.h>

// ---------------- problem constants ----------------
#define Bn  4
#define Sn  8192
#define Dn  1024
#define SDn 512
#define Mn  (Bn * Sn)          // 32768 rows
#define TS  128                // scan tile (rows) == BM
#define NT  (Sn / TS)          // 64 tiles per batch
#define RMS_EPS 1.1920929e-07f

// ---------------- GEMM tiling (fp16 operands) ----------------
#define BM 128
#define BN 128
#define BKH 64                               // K halves per stage (128 B rows)
#define STAGES 3
#define SROWH 72                             // padded halves per row (64+8) -> 144 B
#define ROWB (SROWH * 2)                     // 144 bytes
#define STAGE_BYTES ((BM + BN) * ROWB)       // 36864 B
#define SMEM_BYTES  (STAGES * STAGE_BYTES)   // 110592 B (2 CTAs/SM)

// ---------------- scratch ----------------
__device__ __align__(128) __half g_xh[Mn * Dn];       // x, fp16
__device__ __align__(128) __half g_wb[2 * SDn * Dn];  // interleaved Wg/Wu rows, fp16
__device__ __align__(128) __half g_wo[Dn * SDn];      // W_out fp16
__device__ __align__(128) float  g_z[Mn * SDn];       // z (fp32, scan input)
__device__ __align__(128) __half g_h[Mn * SDn];       // h (fp16, k3b input)
__device__ __align__(128) float  g_tilesum[(Mn / TS) * SDn];
__device__ __align__(128) float  g_rmsinv[Mn];

// ---------------- helpers ----------------
__device__ __forceinline__ uint32_t smem_u32(const void* p) {
    uint32_t a;
    asm("{ .reg .u64 t; cvta.to.shared.u64 t, %1; cvt.u32.u64 %0, t; }" : "=r"(a) : "l"(p));
    return a;
}
__device__ __forceinline__ void cp16(uint32_t d, const void* s) {
    asm volatile("cp.async.cg.shared.global [%0], [%1], 16;" :: "r"(d), "l"(s));
}
#define CP_COMMIT() asm volatile("cp.async.commit_group;" ::: "memory")
#define CP_WAIT(n)  asm volatile("cp.async.wait_group %0;" :: "n"(n) : "memory")

__device__ __forceinline__ void mma_f16(float* c, const uint32_t* a, uint32_t b0, uint32_t b1) {
    asm volatile(
        "mma.sync.aligned.m16n8k16.row.col.f32.f16.f16.f32 "
        "{%0,%1,%2,%3}, {%4,%5,%6,%7}, {%8,%9}, {%0,%1,%2,%3};"
        : "+f"(c[0]), "+f"(c[1]), "+f"(c[2]), "+f"(c[3])
        : "r"(a[0]), "r"(a[1]), "r"(a[2]), "r"(a[3]), "r"(b0), "r"(b1));
}
__device__ __forceinline__ void ldsm4(uint32_t& r0, uint32_t& r1, uint32_t& r2, uint32_t& r3,
                                      uint32_t addr) {
    asm volatile("ldmatrix.sync.aligned.m8n8.x4.shared.b16 {%0,%1,%2,%3}, [%4];"
        : "=r"(r0), "=r"(r1), "=r"(r2), "=r"(r3) : "r"(addr));
}
__device__ __forceinline__ float sigmoidf_fast(float g) {
    return 1.0f / (1.0f + __expf(-g));
}

// ===========================================================================
// conversion kernels: fp32 -> fp16 (RN)
// ===========================================================================
__global__ void k_cvt_h(const float4* __restrict__ src, __half2* __restrict__ dst, int n4) {
    for (int i = blockIdx.x * blockDim.x + threadIdx.x; i < n4; i += gridDim.x * blockDim.x) {
        float4 v = src[i];
        dst[2 * i]     = __floats2half2_rn(v.x, v.y);
        dst[2 * i + 1] = __floats2half2_rn(v.z, v.w);
    }
}
__global__ void k_cvt_pair_h(const float4* __restrict__ wg, const float4* __restrict__ wu,
                             __half2* __restrict__ dst) {
    const int RW = Dn / 4;
    const int total = SDn * RW;
    for (int i = blockIdx.x * blockDim.x + threadIdx.x; i < total; i += gridDim.x * blockDim.x) {
        int r = i / RW, c = i % RW;
        float4 vg = wg[i];
        float4 vu = wu[i];
        size_t dg = (size_t)(2 * r) * (Dn / 2) + 2 * c;
        size_t du = (size_t)(2 * r + 1) * (Dn / 2) + 2 * c;
        dst[dg]     = __floats2half2_rn(vg.x, vg.y);
        dst[dg + 1] = __floats2half2_rn(vg.z, vg.w);
        dst[du]     = __floats2half2_rn(vu.x, vu.y);
        dst[du + 1] = __floats2half2_rn(vu.z, vu.w);
    }
}

// ===========================================================================
// fp16 GEMM mainloop. A: [M x K] rm halves, B: [N x K] rm halves (C = A@B^T).
// CTA tile 128x128, 256 threads, warp grid 4(M) x 2(N), warp tile 32x64.
// 2 CTAs/SM (regs<=128, smem 110.6KB) -> 4 warps/SMSP keep HMMA pipe fed
// across the other CTA's barriers.
// ===========================================================================
struct Frag { float acc[2][8][4]; };

template<int KTOT>
__device__ __forceinline__ void gemm_mainloop(const __half* __restrict__ A,
                                              const __half* __restrict__ B,
                                              int m0, int n0, char* smem, Frag& f) {
    const int t = threadIdx.x;
    const uint32_t sb0 = smem_u32(smem);
    const int lrow = t >> 3;          // 0..31
    const int lseg = t & 7;           // 16B chunk (8 halves) within 128B row

    const int iters = KTOT / BKH;

    #pragma unroll
    for (int i = 0; i < 2; i++)
        #pragma unroll
        for (int j = 0; j < 8; j++)
            #pragma unroll
            for (int q = 0; q < 4; q++) f.acc[i][j][q] = 0.f;

    // stage loader: 8 chunks/thread (i<4 -> A rows 0..127, i>=4 -> B rows 0..127)
    #pragma unroll
    for (int p = 0; p < STAGES - 1; p++) {
        const int k0 = p * BKH;
        #pragma unroll
        for (int i = 0; i < 8; i++) {
            if (i < 4) {
                const int row = 32 * i + lrow;
                cp16(sb0 + p * STAGE_BYTES + row * ROWB + lseg * 16,
                     A + (size_t)(m0 + row) * KTOT + k0 + lseg * 8);
            } else {
                const int row = 32 * (i - 4) + lrow;
                cp16(sb0 + p * STAGE_BYTES + (BM + row) * ROWB + lseg * 16,
                     B + (size_t)(n0 + row) * KTOT + k0 + lseg * 8);
            }
        }
        CP_COMMIT();
    }

    const int wid = t >> 5, lane = t & 31;
    const int wm = wid & 3, wn = wid >> 2;
    const int mrow = wm * 32, nb = wn * 64;

    const uint32_t arow = ((lane >> 3) & 1) * 8 + (lane & 7);
    const uint32_t acolb = ((lane >> 4) & 1) * 16;
    const uint32_t a_off = (mrow + arow) * ROWB + acolb;
    const uint32_t brow = ((lane >> 4) & 1) * 8 + (lane & 7);
    const uint32_t bcolb = ((lane >> 3) & 1) * 16;
    const uint32_t b_off = (BM + nb + brow) * ROWB + bcolb;

    int rs = 0;
    for (int it = 0; it < iters; it++) {
        CP_WAIT(STAGES - 2);
        __syncthreads();

        if (it + STAGES - 1 < iters) {
            int ws = rs + STAGES - 1; if (ws >= STAGES) ws -= STAGES;
            const int k0 = (it + STAGES - 1) * BKH;
            #pragma unroll
            for (int i = 0; i < 8; i++) {
                if (i < 4) {
                    const int row = 32 * i + lrow;
                    cp16(sb0 + ws * STAGE_BYTES + row * ROWB + lseg * 16,
                         A + (size_t)(m0 + row) * KTOT + k0 + lseg * 8);
                } else {
                    const int row = 32 * (i - 4) + lrow;
                    cp16(sb0 + ws * STAGE_BYTES + (BM + row) * ROWB + lseg * 16,
                         B + (size_t)(n0 + row) * KTOT + k0 + lseg * 8);
                }
            }
        }
        CP_COMMIT();

        const uint32_t sbase = sb0 + rs * STAGE_BYTES;

        #pragma unroll
        for (int s = 0; s < BKH / 16; s++) {      // 4 k16-steps
            const uint32_t ko = s * 32;           // 16 halves = 32 bytes
            uint32_t a[2][4];
            #pragma unroll
            for (int mt = 0; mt < 2; mt++)
                ldsm4(a[mt][0], a[mt][1], a[mt][2], a[mt][3],
                      sbase + a_off + mt * 16 * ROWB + ko);
            uint32_t b[8][2];
            #pragma unroll
            for (int p = 0; p < 4; p++)
                ldsm4(b[2*p][0], b[2*p][1], b[2*p+1][0], b[2*p+1][1],
                      sbase + b_off + p * 16 * ROWB + ko);
            #pragma unroll
            for (int nt = 0; nt < 8; nt++)
                #pragma unroll
                for (int mt = 0; mt < 2; mt++)
                    mma_f16(f.acc[mt][nt], a[mt], b[nt][0], b[nt][1]);
        }
        rs++; if (rs == STAGES) rs = 0;
    }
    __syncthreads();
}

// ===========================================================================
// k1: C = x @ Wb^T (interleaved weights, stacked N=1024). Epilogue:
// z = sigmoid(g)*u (fp32), write g_z, per-CTA 128-row tile column sums
// (64 z-cols per CTA).
// ===========================================================================
__global__ void __launch_bounds__(256, 2) k1_gemm() {
    extern __shared__ char smem[];
    const int n0 = blockIdx.x * BN;
    const int m0 = blockIdx.y * BM;
    Frag f;
    gemm_mainloop<Dn>(g_xh, g_wb, m0, n0, smem, f);

    const int t = threadIdx.x;
    const int wid = t >> 5, lane = t & 31;
    const int wm = wid & 3, wn = wid >> 2;
    const int gr = lane >> 2, gc = lane & 3;
    const int zbase = n0 >> 1;             // 64 z-cols per CTA

    float* csum = (float*)smem;
    if (t < 64) csum[t] = 0.f;
    __syncthreads();

    #pragma unroll
    for (int nt = 0; nt < 8; nt++) {
        float cs = 0.f;
        #pragma unroll
        for (int mt = 0; mt < 2; mt++) {
            const int r0 = m0 + wm * 32 + mt * 16 + gr;
            const int zc = zbase + wn * 32 + nt * 4 + gc;
            float z0 = f.acc[mt][nt][1] * sigmoidf_fast(f.acc[mt][nt][0]);
            float z1 = f.acc[mt][nt][3] * sigmoidf_fast(f.acc[mt][nt][2]);
            g_z[(size_t)r0 * SDn + zc] = z0;
            g_z[(size_t)(r0 + 8) * SDn + zc] = z1;
            cs += z0 + z1;
        }
        cs += __shfl_xor_sync(0xffffffffu, cs, 4);
        cs += __shfl_xor_sync(0xffffffffu, cs, 8);
        cs += __shfl_xor_sync(0xffffffffu, cs, 16);
        if (gr == 0)
            atomicAdd(&csum[wn * 32 + nt * 4 + gc], cs);
    }
    __syncthreads();
    if (t < 64)
        g_tilesum[(size_t)blockIdx.y * SDn + zbase + t] = csum[t];
}

// ===========================================================================
// k2: exclusive prefix over tiles per (b,k) channel (register-batched loads)
// ===========================================================================
__global__ void k2_tileprefix() {
    const int idx = blockIdx.x * blockDim.x + threadIdx.x;
    const size_t base = (size_t)(idx / SDn) * NT * SDn + (idx % SDn);
    float v[NT];
    #pragma unroll
    for (int t = 0; t < NT; t++) v[t] = g_tilesum[base + (size_t)t * SDn];
    float run = 0.f;
    #pragma unroll
    for (int t = 0; t < NT; t++) {
        float nv = run + v[t];
        g_tilesum[base + (size_t)t * SDn] = run;
        run = nv;
    }
}

// ===========================================================================
// k3a: in-tile scan + /denom; write h as fp16 to g_h; per-row rms_inv
// ===========================================================================
__global__ void __launch_bounds__(512) k3a_scan() {
    const int mt = blockIdx.x;
    const int t = mt & (NT - 1);
    const int k = threadIdx.x;
    const int warp = k >> 5, lane = k & 31;
    const int base = mt * TS;

    __shared__ float ssp[TS][16];

    float carry = g_tilesum[(size_t)mt * SDn + k];

    #pragma unroll 4
    for (int r = 0; r < TS; r++) {
        const size_t off = (size_t)(base + r) * SDn + k;
        carry += g_z[off];
        float h = __fdividef(carry, (float)(t * TS + r + 1));
        __half hh = __float2half_rn(h);
        g_h[off] = hh;
        float hr = __half2float(hh);
        float sq = hr * hr;
        #pragma unroll
        for (int o = 16; o > 0; o >>= 1) sq += __shfl_xor_sync(0xffffffffu, sq, o);
        if (lane == 0) ssp[r][warp] = sq;
    }
    __syncthreads();
    if (k < TS) {
        float s = 0.f;
        #pragma unroll
        for (int w = 0; w < 16; w++) s += ssp[k][w];
        g_rmsinv[base + k] = rsqrtf(s * (1.0f / SDn) + RMS_EPS);
    }
}

// ===========================================================================
// k3b: out = rms_inv[m] * (h @ Wo^T), M=32768, N=1024, K=512 (fp16 inputs)
// ===========================================================================
__global__ void __launch_bounds__(256, 2) k3b_gemm(float* __restrict__ out) {
    extern __shared__ char smem[];
    const int n0 = blockIdx.x * BN;
    const int m0 = blockIdx.y * BM;
    Frag f;
    gemm_mainloop<SDn>(g_h, g_wo, m0, n0, smem, f);

    const int t = threadIdx.x;
    const int wid = t >> 5, lane = t & 31;
    const int wm = wid & 3, wn = wid >> 2;
    const int gr = lane >> 2, gc = lane & 3;

    #pragma unroll
    for (int mt = 0; mt < 2; mt++) {
        const int r0 = m0 + wm * 32 + mt * 16 + gr;
        const float ri0 = g_rmsinv[r0];
        const float ri1 = g_rmsinv[r0 + 8];
        #pragma unroll
        for (int nt = 0; nt < 8; nt++) {
            const int col = n0 + wn * 64 + nt * 8 + gc * 2;
            float2 v0 = { f.acc[mt][nt][0] * ri0, f.acc[mt][nt][1] * ri0 };
            float2 v1 = { f.acc[mt][nt][2] * ri1, f.acc[mt][nt][3] * ri1 };
            *(float2*)&out[(size_t)r0 * Dn + col] = v0;
            *(float2*)&out[(size_t)(r0 + 8) * Dn + col] = v1;
        }
    }
}

// ===========================================================================
// host side
// ===========================================================================
extern "C" void kernel_launch(void* const* d_in, const int* in_sizes, int n_in,
                              void* d_out, int out_size) {
    const float* x  = (const float*)d_in[0];
    const float* Wu = (const float*)d_in[1];
    const float* Wg = (const float*)d_in[2];
    const float* Wo = (const float*)d_in[3];
    float* out = (float*)d_out;

    void *pxh, *pwb, *pwo;
    cudaGetSymbolAddress(&pxh, g_xh);
    cudaGetSymbolAddress(&pwb, g_wb);
    cudaGetSymbolAddress(&pwo, g_wo);

    cudaFuncSetAttribute(k1_gemm,  cudaFuncAttributeMaxDynamicSharedMemorySize, SMEM_BYTES);
    cudaFuncSetAttribute(k3b_gemm, cudaFuncAttributeMaxDynamicSharedMemorySize, SMEM_BYTES);

    k_cvt_h<<<4096, 256>>>((const float4*)x, (__half2*)pxh, Mn * Dn / 4);
    k_cvt_pair_h<<<512, 256>>>((const float4*)Wg, (const float4*)Wu, (__half2*)pwb);
    k_cvt_h<<<512, 256>>>((const float4*)Wo, (__half2*)pwo, Dn * SDn / 4);

    k1_gemm<<<dim3(2 * SDn / BN, Mn / BM), 256, SMEM_BYTES>>>();
    k2_tileprefix<<<(Bn * SDn) / 256, 256>>>();
    k3a_scan<<<Mn / TS, 512>>>();
    k3b_gemm<<<dim3(Dn / BN, Mn / BM), 256, SMEM_BYTES>>>(out);
}

// round 11
// speedup vs baseline: 2.0711x; 1.0401x over previous
#include <cuda_runtime.h>
#include <cuda_fp16.h>
#include <cstdint>
#include <math.h>

// ---------------- problem constants ----------------
#define Bn  4
#define Sn  8192
#define Dn  1024
#define SDn 512
#define Mn  (Bn * Sn)          // 32768 rows
#define TS  128                // scan tile (rows) == BM
#define NT  (Sn / TS)          // 64 tiles per batch
#define RMS_EPS 1.1920929e-07f

// ---------------- GEMM tiling (fp16 operands) ----------------
#define BM 128
#define BN 128
#define BKH 64                               // K halves per stage (128 B rows)
#define STAGES 3
#define SROWH 72                             // padded halves per row (64+8) -> 144 B
#define ROWB (SROWH * 2)                     // 144 bytes
#define STAGE_BYTES ((BM + BN) * ROWB)       // 36864 B
#define SMEM_BYTES  (STAGES * STAGE_BYTES)   // 110592 B (2 CTAs/SM)

// ---------------- scratch ----------------
__device__ __align__(128) __half g_xh[Mn * Dn];       // x, fp16
__device__ __align__(128) __half g_wb[2 * SDn * Dn];  // interleaved Wg/Wu rows, fp16
__device__ __align__(128) __half g_wo[Dn * SDn];      // W_out fp16
__device__ __align__(128) __half g_zh[Mn * SDn];      // z then h (fp16, in place)
__device__ __align__(128) float  g_tilesum[(Mn / TS) * SDn];
__device__ __align__(128) float  g_rmsinv[Mn];

// ---------------- helpers ----------------
__device__ __forceinline__ uint32_t smem_u32(const void* p) {
    uint32_t a;
    asm("{ .reg .u64 t; cvta.to.shared.u64 t, %1; cvt.u32.u64 %0, t; }" : "=r"(a) : "l"(p));
    return a;
}
__device__ __forceinline__ void cp16(uint32_t d, const void* s) {
    asm volatile("cp.async.cg.shared.global [%0], [%1], 16;" :: "r"(d), "l"(s));
}
#define CP_COMMIT() asm volatile("cp.async.commit_group;" ::: "memory")
#define CP_WAIT(n)  asm volatile("cp.async.wait_group %0;" :: "n"(n) : "memory")

__device__ __forceinline__ void mma_f16(float* c, const uint32_t* a, uint32_t b0, uint32_t b1) {
    asm volatile(
        "mma.sync.aligned.m16n8k16.row.col.f32.f16.f16.f32 "
        "{%0,%1,%2,%3}, {%4,%5,%6,%7}, {%8,%9}, {%0,%1,%2,%3};"
        : "+f"(c[0]), "+f"(c[1]), "+f"(c[2]), "+f"(c[3])
        : "r"(a[0]), "r"(a[1]), "r"(a[2]), "r"(a[3]), "r"(b0), "r"(b1));
}
__device__ __forceinline__ void ldsm4(uint32_t& r0, uint32_t& r1, uint32_t& r2, uint32_t& r3,
                                      uint32_t addr) {
    asm volatile("ldmatrix.sync.aligned.m8n8.x4.shared.b16 {%0,%1,%2,%3}, [%4];"
        : "=r"(r0), "=r"(r1), "=r"(r2), "=r"(r3) : "r"(addr));
}
__device__ __forceinline__ float sigmoidf_fast(float g) {
    return 1.0f / (1.0f + __expf(-g));
}

// ===========================================================================
// conversion kernels: fp32 -> fp16 (RN)
// ===========================================================================
__global__ void k_cvt_h(const float4* __restrict__ src, __half2* __restrict__ dst, int n4) {
    for (int i = blockIdx.x * blockDim.x + threadIdx.x; i < n4; i += gridDim.x * blockDim.x) {
        float4 v = src[i];
        dst[2 * i]     = __floats2half2_rn(v.x, v.y);
        dst[2 * i + 1] = __floats2half2_rn(v.z, v.w);
    }
}
__global__ void k_cvt_pair_h(const float4* __restrict__ wg, const float4* __restrict__ wu,
                             __half2* __restrict__ dst) {
    const int RW = Dn / 4;
    const int total = SDn * RW;
    for (int i = blockIdx.x * blockDim.x + threadIdx.x; i < total; i += gridDim.x * blockDim.x) {
        int r = i / RW, c = i % RW;
        float4 vg = wg[i];
        float4 vu = wu[i];
        size_t dg = (size_t)(2 * r) * (Dn / 2) + 2 * c;
        size_t du = (size_t)(2 * r + 1) * (Dn / 2) + 2 * c;
        dst[dg]     = __floats2half2_rn(vg.x, vg.y);
        dst[dg + 1] = __floats2half2_rn(vg.z, vg.w);
        dst[du]     = __floats2half2_rn(vu.x, vu.y);
        dst[du + 1] = __floats2half2_rn(vu.z, vu.w);
    }
}

// ===========================================================================
// fp16 GEMM mainloop. A: [M x K] rm halves, B: [N x K] rm halves (C = A@B^T).
// CTA tile 128x128, 256 threads, warp grid 4(M) x 2(N), warp tile 32x64.
// 2 CTAs/SM.
// ===========================================================================
struct Frag { float acc[2][8][4]; };

template<int KTOT>
__device__ __forceinline__ void gemm_mainloop(const __half* __restrict__ A,
                                              const __half* __restrict__ B,
                                              int m0, int n0, char* smem, Frag& f) {
    const int t = threadIdx.x;
    const uint32_t sb0 = smem_u32(smem);
    const int lrow = t >> 3;          // 0..31
    const int lseg = t & 7;           // 16B chunk (8 halves) within 128B row

    const int iters = KTOT / BKH;

    #pragma unroll
    for (int i = 0; i < 2; i++)
        #pragma unroll
        for (int j = 0; j < 8; j++)
            #pragma unroll
            for (int q = 0; q < 4; q++) f.acc[i][j][q] = 0.f;

    #pragma unroll
    for (int p = 0; p < STAGES - 1; p++) {
        const int k0 = p * BKH;
        #pragma unroll
        for (int i = 0; i < 8; i++) {
            if (i < 4) {
                const int row = 32 * i + lrow;
                cp16(sb0 + p * STAGE_BYTES + row * ROWB + lseg * 16,
                     A + (size_t)(m0 + row) * KTOT + k0 + lseg * 8);
            } else {
                const int row = 32 * (i - 4) + lrow;
                cp16(sb0 + p * STAGE_BYTES + (BM + row) * ROWB + lseg * 16,
                     B + (size_t)(n0 + row) * KTOT + k0 + lseg * 8);
            }
        }
        CP_COMMIT();
    }

    const int wid = t >> 5, lane = t & 31;
    const int wm = wid & 3, wn = wid >> 2;
    const int mrow = wm * 32, nb = wn * 64;

    const uint32_t arow = ((lane >> 3) & 1) * 8 + (lane & 7);
    const uint32_t acolb = ((lane >> 4) & 1) * 16;
    const uint32_t a_off = (mrow + arow) * ROWB + acolb;
    const uint32_t brow = ((lane >> 4) & 1) * 8 + (lane & 7);
    const uint32_t bcolb = ((lane >> 3) & 1) * 16;
    const uint32_t b_off = (BM + nb + brow) * ROWB + bcolb;

    int rs = 0;
    for (int it = 0; it < iters; it++) {
        CP_WAIT(STAGES - 2);
        __syncthreads();

        if (it + STAGES - 1 < iters) {
            int ws = rs + STAGES - 1; if (ws >= STAGES) ws -= STAGES;
            const int k0 = (it + STAGES - 1) * BKH;
            #pragma unroll
            for (int i = 0; i < 8; i++) {
                if (i < 4) {
                    const int row = 32 * i + lrow;
                    cp16(sb0 + ws * STAGE_BYTES + row * ROWB + lseg * 16,
                         A + (size_t)(m0 + row) * KTOT + k0 + lseg * 8);
                } else {
                    const int row = 32 * (i - 4) + lrow;
                    cp16(sb0 + ws * STAGE_BYTES + (BM + row) * ROWB + lseg * 16,
                         B + (size_t)(n0 + row) * KTOT + k0 + lseg * 8);
                }
            }
        }
        CP_COMMIT();

        const uint32_t sbase = sb0 + rs * STAGE_BYTES;

        #pragma unroll
        for (int s = 0; s < BKH / 16; s++) {      // 4 k16-steps
            const uint32_t ko = s * 32;
            uint32_t a[2][4];
            #pragma unroll
            for (int mt = 0; mt < 2; mt++)
                ldsm4(a[mt][0], a[mt][1], a[mt][2], a[mt][3],
                      sbase + a_off + mt * 16 * ROWB + ko);
            uint32_t b[8][2];
            #pragma unroll
            for (int p = 0; p < 4; p++)
                ldsm4(b[2*p][0], b[2*p][1], b[2*p+1][0], b[2*p+1][1],
                      sbase + b_off + p * 16 * ROWB + ko);
            #pragma unroll
            for (int nt = 0; nt < 8; nt++)
                #pragma unroll
                for (int mt = 0; mt < 2; mt++)
                    mma_f16(f.acc[mt][nt], a[mt], b[nt][0], b[nt][1]);
        }
        rs++; if (rs == STAGES) rs = 0;
    }
    __syncthreads();
}

// ===========================================================================
// k1: C = x @ Wb^T. Epilogue: z = sigmoid(g)*u rounded to fp16 -> g_zh,
// per-CTA 128-row tile column sums computed from the ROUNDED values.
// ===========================================================================
__global__ void __launch_bounds__(256, 2) k1_gemm() {
    extern __shared__ char smem[];
    const int n0 = blockIdx.x * BN;
    const int m0 = blockIdx.y * BM;
    Frag f;
    gemm_mainloop<Dn>(g_xh, g_wb, m0, n0, smem, f);

    const int t = threadIdx.x;
    const int wid = t >> 5, lane = t & 31;
    const int wm = wid & 3, wn = wid >> 2;
    const int gr = lane >> 2, gc = lane & 3;
    const int zbase = n0 >> 1;             // 64 z-cols per CTA

    float* csum = (float*)smem;
    if (t < 64) csum[t] = 0.f;
    __syncthreads();

    #pragma unroll
    for (int nt = 0; nt < 8; nt++) {
        float cs = 0.f;
        #pragma unroll
        for (int mt = 0; mt < 2; mt++) {
            const int r0 = m0 + wm * 32 + mt * 16 + gr;
            const int zc = zbase + wn * 32 + nt * 4 + gc;
            __half h0 = __float2half_rn(f.acc[mt][nt][1] * sigmoidf_fast(f.acc[mt][nt][0]));
            __half h1 = __float2half_rn(f.acc[mt][nt][3] * sigmoidf_fast(f.acc[mt][nt][2]));
            g_zh[(size_t)r0 * SDn + zc] = h0;
            g_zh[(size_t)(r0 + 8) * SDn + zc] = h1;
            cs += __half2float(h0) + __half2float(h1);
        }
        cs += __shfl_xor_sync(0xffffffffu, cs, 4);
        cs += __shfl_xor_sync(0xffffffffu, cs, 8);
        cs += __shfl_xor_sync(0xffffffffu, cs, 16);
        if (gr == 0)
            atomicAdd(&csum[wn * 32 + nt * 4 + gc], cs);
    }
    __syncthreads();
    if (t < 64)
        g_tilesum[(size_t)blockIdx.y * SDn + zbase + t] = csum[t];
}

// ===========================================================================
// k2: exclusive prefix over tiles per (b,k) channel (register-batched loads)
// ===========================================================================
__global__ void k2_tileprefix() {
    const int idx = blockIdx.x * blockDim.x + threadIdx.x;
    const size_t base = (size_t)(idx / SDn) * NT * SDn + (idx % SDn);
    float v[NT];
    #pragma unroll
    for (int t = 0; t < NT; t++) v[t] = g_tilesum[base + (size_t)t * SDn];
    float run = 0.f;
    #pragma unroll
    for (int t = 0; t < NT; t++) {
        float nv = run + v[t];
        g_tilesum[base + (size_t)t * SDn] = run;
        run = nv;
    }
}

// ===========================================================================
// k3a: pure streaming scan, in place on g_zh (fp16 in / fp16 out).
// 256 threads x 2 columns (half2), fp32 carries. One block per 128-row tile.
// ===========================================================================
__global__ void __launch_bounds__(256) k3a_scan() {
    const int mt = blockIdx.x;
    const int t = mt & (NT - 1);
    const int k2i = threadIdx.x;           // half2 column index (0..255)
    const int base = mt * TS;

    const float2 ts = *(const float2*)&g_tilesum[(size_t)mt * SDn + 2 * k2i];
    float c0 = ts.x, c1 = ts.y;

    __half2* zp = (__half2*)g_zh + ((size_t)base * SDn >> 1) + k2i;

    #pragma unroll 8
    for (int r = 0; r < TS; r++) {
        float2 zv = __half22float2(zp[0]);
        c0 += zv.x;
        c1 += zv.y;
        const float inv = __frcp_rn((float)(t * TS + r + 1));
        zp[0] = __floats2half2_rn(c0 * inv, c1 * inv);
        zp += SDn / 2;
    }
}

// ===========================================================================
// k_rms: per-row rms_inv from fp16 h. Warp per row, 8 rows per block.
// ===========================================================================
__global__ void __launch_bounds__(256) k_rms() {
    const int row = blockIdx.x * 8 + (threadIdx.x >> 5);
    const int lane = threadIdx.x & 31;
    const uint4* p = (const uint4*)(g_zh + (size_t)row * SDn);

    float s = 0.f;
    #pragma unroll
    for (int i = 0; i < 2; i++) {
        uint4 v = p[lane + 32 * i];          // 8 halves
        float2 a0 = __half22float2(*(__half2*)&v.x);
        float2 a1 = __half22float2(*(__half2*)&v.y);
        float2 a2 = __half22float2(*(__half2*)&v.z);
        float2 a3 = __half22float2(*(__half2*)&v.w);
        s += a0.x*a0.x + a0.y*a0.y + a1.x*a1.x + a1.y*a1.y
           + a2.x*a2.x + a2.y*a2.y + a3.x*a3.x + a3.y*a3.y;
    }
    #pragma unroll
    for (int o = 16; o > 0; o >>= 1) s += __shfl_xor_sync(0xffffffffu, s, o);
    if (lane == 0)
        g_rmsinv[row] = rsqrtf(s * (1.0f / SDn) + RMS_EPS);
}

// ===========================================================================
// k3b: out = rms_inv[m] * (h @ Wo^T), M=32768, N=1024, K=512 (fp16 inputs)
// ===========================================================================
__global__ void __launch_bounds__(256, 2) k3b_gemm(float* __restrict__ out) {
    extern __shared__ char smem[];
    const int n0 = blockIdx.x * BN;
    const int m0 = blockIdx.y * BM;
    Frag f;
    gemm_mainloop<SDn>(g_zh, g_wo, m0, n0, smem, f);

    const int t = threadIdx.x;
    const int wid = t >> 5, lane = t & 31;
    const int wm = wid & 3, wn = wid >> 2;
    const int gr = lane >> 2, gc = lane & 3;

    #pragma unroll
    for (int mt = 0; mt < 2; mt++) {
        const int r0 = m0 + wm * 32 + mt * 16 + gr;
        const float ri0 = g_rmsinv[r0];
        const float ri1 = g_rmsinv[r0 + 8];
        #pragma unroll
        for (int nt = 0; nt < 8; nt++) {
            const int col = n0 + wn * 64 + nt * 8 + gc * 2;
            float2 v0 = { f.acc[mt][nt][0] * ri0, f.acc[mt][nt][1] * ri0 };
            float2 v1 = { f.acc[mt][nt][2] * ri1, f.acc[mt][nt][3] * ri1 };
            *(float2*)&out[(size_t)r0 * Dn + col] = v0;
            *(float2*)&out[(size_t)(r0 + 8) * Dn + col] = v1;
        }
    }
}

// ===========================================================================
// host side
// ===========================================================================
extern "C" void kernel_launch(void* const* d_in, const int* in_sizes, int n_in,
                              void* d_out, int out_size) {
    const float* x  = (const float*)d_in[0];
    const float* Wu = (const float*)d_in[1];
    const float* Wg = (const float*)d_in[2];
    const float* Wo = (const float*)d_in[3];
    float* out = (float*)d_out;

    void *pxh, *pwb, *pwo;
    cudaGetSymbolAddress(&pxh, g_xh);
    cudaGetSymbolAddress(&pwb, g_wb);
    cudaGetSymbolAddress(&pwo, g_wo);

    cudaFuncSetAttribute(k1_gemm,  cudaFuncAttributeMaxDynamicSharedMemorySize, SMEM_BYTES);
    cudaFuncSetAttribute(k3b_gemm, cudaFuncAttributeMaxDynamicSharedMemorySize, SMEM_BYTES);

    k_cvt_h<<<4096, 256>>>((const float4*)x, (__half2*)pxh, Mn * Dn / 4);
    k_cvt_pair_h<<<512, 256>>>((const float4*)Wg, (const float4*)Wu, (__half2*)pwb);
    k_cvt_h<<<512, 256>>>((const float4*)Wo, (__half2*)pwo, Dn * SDn / 4);

    k1_gemm<<<dim3(2 * SDn / BN, Mn / BM), 256, SMEM_BYTES>>>();
    k2_tileprefix<<<(Bn * SDn) / 256, 256>>>();
    k3a_scan<<<Mn / TS, 256>>>();
    k_rms<<<Mn / 8, 256>>>();
    k3b_gemm<<<dim3(Dn / BN, Mn / BM), 256, SMEM_BYTES>>>(out);
}